// round 1
// baseline (speedup 1.0000x reference)
#include <cuda_runtime.h>
#include <math.h>

// Problem constants
#define NB   4
#define HH   64
#define WWD  64
#define CC   256
#define GG   8
#define HP   66            // padded spatial
#define LPIX 4096          // 64*64
#define NPIX 16384         // NB*LPIX

// ---------------- scratch (device globals; no allocation allowed) ----------
__device__ float g_xs [NPIX * CC];            // x NHWC
__device__ float g_xp [NB * HP * HP * CC];    // padded x_proj
__device__ float g_t  [NPIX * CC];            // post dwconv+LN+GELU
__device__ float g_off[NPIX * 144];
__device__ float g_msk[NPIX * 72];
__device__ float g_y  [NPIX * CC];
__device__ float g_y2 [NPIX * CC];
__device__ float g_dn [NB * 32 * 32 * CC];

// ---------------- helpers ---------------------------------------------------
__device__ __forceinline__ void block_reduce2(float &a, float &b, float* sh) {
    // blockDim.x == 256
    int lane = threadIdx.x & 31, wid = threadIdx.x >> 5;
#pragma unroll
    for (int o = 16; o; o >>= 1) {
        a += __shfl_down_sync(0xffffffffu, a, o);
        b += __shfl_down_sync(0xffffffffu, b, o);
    }
    if (lane == 0) { sh[wid] = a; sh[8 + wid] = b; }
    __syncthreads();
    if (wid == 0) {
        a = (lane < 8) ? sh[lane] : 0.f;
        b = (lane < 8) ? sh[8 + lane] : 0.f;
#pragma unroll
        for (int o = 4; o; o >>= 1) {
            a += __shfl_down_sync(0xffffffffu, a, o);
            b += __shfl_down_sync(0xffffffffu, b, o);
        }
        if (lane == 0) { sh[16] = a; sh[17] = b; }
    }
    __syncthreads();
    a = sh[16]; b = sh[17];
}

// ---------------- NCHW -> NHWC transpose -----------------------------------
__global__ void k_transpose(const float* __restrict__ x) {
    __shared__ float tile[32][33];
    int n  = blockIdx.z;
    int c0 = blockIdx.x * 32;
    int p0 = blockIdx.y * 32;
    int tx = threadIdx.x, ty = threadIdx.y;   // 32 x 8
#pragma unroll
    for (int j = 0; j < 32; j += 8)
        tile[ty + j][tx] = x[(size_t)(n * CC + c0 + ty + j) * LPIX + p0 + tx];
    __syncthreads();
#pragma unroll
    for (int j = 0; j < 32; j += 8)
        g_xs[(size_t)(n * LPIX + p0 + ty + j) * CC + c0 + tx] = tile[tx][ty + j];
}

// ---------------- zero padded buffer ----------------------------------------
__global__ void k_zero_xp() {
    int i = blockIdx.x * blockDim.x + threadIdx.x;
    const int total4 = (NB * HP * HP * CC) / 4;
    if (i < total4)
        reinterpret_cast<float4*>(g_xp)[i] = make_float4(0.f, 0.f, 0.f, 0.f);
}

// ---------------- unified tiled GEMM / implicit-im2col conv -----------------
// C[M,N] = A(M,K) @ B(K,N) + bias
// mode 0: A is plain row-major MxK
// mode 1: implicit im2col: A is NHWC 64x64x256 image; K = 9*256;
//         row m -> (n, oh, ow) with OW = 1<<owbits; input pos = oh*stride+kh-1
// padout: write into g_xp-style padded 66x66x256 layout (h+1, w+1)
__global__ void k_gemm(const float* __restrict__ A, const float* __restrict__ B,
                       const float* __restrict__ bias, float* __restrict__ Cout,
                       int N, int K, int mode, int owbits, int stride, int padout)
{
    __shared__ float As[64][16];
    __shared__ float Bs[16][64];
    const int tid = threadIdx.x;
    const int m0 = blockIdx.y * 64;
    const int n0 = blockIdx.x * 64;
    const int ty = tid >> 4, tx = tid & 15;

    // A-load mapping: one fixed row per thread, 4 consecutive k
    const int amr = tid >> 2;
    const int akc = (tid & 3) << 2;
    const int am  = m0 + amr;
    int a_n = 0, a_oh = 0, a_ow = 0;
    const float* Arow = A;
    if (mode == 0) {
        Arow = A + (size_t)am * K;
    } else {
        int ow = 1 << owbits;
        a_n  = am >> (2 * owbits);
        int hw = am & ((1 << (2 * owbits)) - 1);
        a_oh = hw >> owbits;
        a_ow = hw & (ow - 1);
    }
    const int bkr = tid >> 4;          // 0..15
    const int bnc = (tid & 15) << 2;   // 0..60

    float acc[4][4];
#pragma unroll
    for (int i = 0; i < 4; i++)
#pragma unroll
        for (int j = 0; j < 4; j++) acc[i][j] = 0.f;

    for (int k0 = 0; k0 < K; k0 += 16) {
        float4 av;
        if (mode == 0) {
            av = *reinterpret_cast<const float4*>(Arow + k0 + akc);
        } else {
            int tap = k0 >> 8;                 // whole chunk inside one tap
            int kh = tap / 3, kw = tap - 3 * kh;
            int iy = a_oh * stride + kh - 1;
            int ix = a_ow * stride + kw - 1;
            int ci = (k0 & 255) + akc;
            if ((unsigned)iy < 64u && (unsigned)ix < 64u)
                av = *reinterpret_cast<const float4*>(
                        A + ((size_t)((a_n * 64 + iy) * 64 + ix)) * 256 + ci);
            else
                av = make_float4(0.f, 0.f, 0.f, 0.f);
        }
        *reinterpret_cast<float4*>(&As[amr][akc]) = av;

#pragma unroll
        for (int j = 0; j < 4; j++) {
            int col = n0 + bnc + j;
            Bs[bkr][bnc + j] = (col < N) ? B[(size_t)(k0 + bkr) * N + col] : 0.f;
        }
        __syncthreads();

#pragma unroll
        for (int kk = 0; kk < 16; kk++) {
            float a_[4];
#pragma unroll
            for (int i = 0; i < 4; i++) a_[i] = As[ty * 4 + i][kk];
            float4 bv = *reinterpret_cast<const float4*>(&Bs[kk][tx * 4]);
            float b_[4] = {bv.x, bv.y, bv.z, bv.w};
#pragma unroll
            for (int i = 0; i < 4; i++)
#pragma unroll
                for (int j = 0; j < 4; j++)
                    acc[i][j] += a_[i] * b_[j];
        }
        __syncthreads();
    }

#pragma unroll
    for (int i = 0; i < 4; i++) {
        int m = m0 + ty * 4 + i;
        float* outrow;
        if (padout) {
            int n = m >> 12;
            int h = (m >> 6) & 63;
            int w = m & 63;
            outrow = Cout + ((size_t)(n * HP + h + 1) * HP + (w + 1)) * CC;
        } else {
            outrow = Cout + (size_t)m * N;
        }
#pragma unroll
        for (int j = 0; j < 4; j++) {
            int col = n0 + tx * 4 + j;
            if (col < N) outrow[col] = acc[i][j] + bias[col];
        }
    }
}

// ---------------- depthwise 3x3 + LayerNorm + exact GELU --------------------
__global__ void k_dw(const float* __restrict__ dww, const float* __restrict__ dwb,
                     const float* __restrict__ lng, const float* __restrict__ lnb)
{
    int pix = blockIdx.x;
    int c   = threadIdx.x;
    int n = pix >> 12, h = (pix >> 6) & 63, w = pix & 63;
    float acc = dwb[c];
#pragma unroll
    for (int kh = 0; kh < 3; kh++) {
        int y = h + kh - 1;
        if ((unsigned)y >= 64u) continue;
#pragma unroll
        for (int kw = 0; kw < 3; kw++) {
            int x = w + kw - 1;
            if ((unsigned)x >= 64u) continue;
            acc += g_xs[((size_t)((n * 64 + y) * 64 + x)) * 256 + c] *
                   dww[(kh * 3 + kw) * 256 + c];
        }
    }
    __shared__ float sh[32];
    float s = acc, ss = acc * acc;
    block_reduce2(s, ss, sh);
    float mean = s * (1.f / 256.f);
    float var  = ss * (1.f / 256.f) - mean * mean;
    float rstd = rsqrtf(var + 1e-5f);
    float v = (acc - mean) * rstd * lng[c] + lnb[c];
    v = 0.5f * v * (1.f + erff(v * 0.70710678118654752440f));   // exact GELU
    g_t[(size_t)pix * 256 + c] = v;
}

// ---------------- deformable bilinear sampling + mask aggregation -----------
__global__ void k_sample()
{
    int pix  = blockIdx.x;
    int g    = threadIdx.x >> 5;
    int lane = threadIdx.x & 31;
    int n = pix >> 12, h = (pix >> 6) & 63, w = pix & 63;

    const float* ml = g_msk + (size_t)pix * 72 + g * 9;
    float e[9], mx = -1e30f, s = 0.f;
#pragma unroll
    for (int p = 0; p < 9; p++) mx = fmaxf(mx, ml[p]);
#pragma unroll
    for (int p = 0; p < 9; p++) { e[p] = expf(ml[p] - mx); s += e[p]; }
    float inv = 1.f / s;

    const float* off = g_off + (size_t)pix * 144 + g * 18;
    const float* img = g_xp + (size_t)n * HP * HP * CC + g * 32 + lane;
    float acc = 0.f;
#pragma unroll
    for (int p = 0; p < 9; p++) {
        // px = w + 1 + (p/3 - 1) + offx ; py = h + 1 + (p%3 - 1) + offy
        float px = (float)(w + p / 3) + off[2 * p];
        float py = (float)(h + p % 3) + off[2 * p + 1];
        float wgt = e[p] * inv;
        float x0f = floorf(px), y0f = floorf(py);
        int x0 = (int)x0f, y0 = (int)y0f;
        float fx = px - x0f, fy = py - y0f;
#pragma unroll
        for (int dy = 0; dy < 2; dy++) {
            int yy = y0 + dy;
            if ((unsigned)yy >= (unsigned)HP) continue;
            float wy = dy ? fy : 1.f - fy;
#pragma unroll
            for (int dx = 0; dx < 2; dx++) {
                int xx = x0 + dx;
                if ((unsigned)xx >= (unsigned)HP) continue;
                float wx = dx ? fx : 1.f - fx;
                acc += img[((size_t)yy * HP + xx) * CC] * (wx * wy * wgt);
            }
        }
    }
    g_y[(size_t)pix * 256 + g * 32 + lane] = acc;
}

// ---------------- GroupNorm(32 groups) [+SiLU] [+NCHW out] ------------------
__global__ void k_gn(const float* __restrict__ in, float* __restrict__ out,
                     const float* __restrict__ gamma, const float* __restrict__ beta,
                     int HWn, int do_silu, int out_nchw, int Wd)
{
    int n = blockIdx.x >> 5;
    int g = blockIdx.x & 31;
    int cnt = HWn * 8;
    const float* base = in + (size_t)n * HWn * 256 + g * 8;
    float s = 0.f, ss = 0.f;
    for (int i = threadIdx.x; i < cnt; i += 256) {
        float v = base[(size_t)(i >> 3) * 256 + (i & 7)];
        s += v; ss += v * v;
    }
    __shared__ float sh[32];
    block_reduce2(s, ss, sh);
    float mean = s / (float)cnt;
    float rstd = rsqrtf(ss / (float)cnt - mean * mean + 1e-5f);
    for (int i = threadIdx.x; i < cnt; i += 256) {
        int l = i >> 3, c = i & 7;
        float v = base[(size_t)l * 256 + c];
        v = (v - mean) * rstd * gamma[g * 8 + c] + beta[g * 8 + c];
        if (do_silu) v = v * (1.f / (1.f + expf(-v)));
        if (out_nchw)
            out[(((size_t)n * 256 + g * 8 + c) * Wd + (l / Wd)) * Wd + (l % Wd)] = v;
        else
            out[((size_t)n * HWn + l) * 256 + g * 8 + c] = v;
    }
}

// ---------------- launch -----------------------------------------------------
extern "C" void kernel_launch(void* const* d_in, const int* in_sizes, int n_in,
                              void* d_out, int out_size)
{
    const float* x      = (const float*)d_in[0];
    const float* w_in   = (const float*)d_in[1];
    const float* b_in   = (const float*)d_in[2];
    const float* dw_w   = (const float*)d_in[3];
    const float* dw_b   = (const float*)d_in[4];
    const float* ln_g   = (const float*)d_in[5];
    const float* ln_b   = (const float*)d_in[6];
    const float* w_off  = (const float*)d_in[7];
    const float* b_off  = (const float*)d_in[8];
    const float* w_mask = (const float*)d_in[9];
    const float* b_mask = (const float*)d_in[10];
    const float* w_out  = (const float*)d_in[11];
    const float* b_out  = (const float*)d_in[12];
    const float* gn1_g  = (const float*)d_in[13];
    const float* gn1_b  = (const float*)d_in[14];
    const float* c1_w   = (const float*)d_in[15];
    const float* c1_b   = (const float*)d_in[16];
    const float* gn2_g  = (const float*)d_in[17];
    const float* gn2_b  = (const float*)d_in[18];
    const float* dn_w   = (const float*)d_in[19];
    const float* dn_b   = (const float*)d_in[20];
    const float* gn3_g  = (const float*)d_in[21];
    const float* gn3_b  = (const float*)d_in[22];

    float *xs, *xp, *t, *off, *msk, *y, *y2, *dn;
    cudaGetSymbolAddress((void**)&xs,  g_xs);
    cudaGetSymbolAddress((void**)&xp,  g_xp);
    cudaGetSymbolAddress((void**)&t,   g_t);
    cudaGetSymbolAddress((void**)&off, g_off);
    cudaGetSymbolAddress((void**)&msk, g_msk);
    cudaGetSymbolAddress((void**)&y,   g_y);
    cudaGetSymbolAddress((void**)&y2,  g_y2);
    cudaGetSymbolAddress((void**)&dn,  g_dn);

    // 1. NCHW -> NHWC
    k_transpose<<<dim3(8, 128, 4), dim3(32, 8)>>>(x);
    // 2. zero padded buffer (borders must be 0 each run)
    k_zero_xp<<<(NB * HP * HP * CC / 4 + 255) / 256, 256>>>();
    // 3. input projection -> padded xp
    k_gemm<<<dim3(4, 256), 256>>>(xs, w_in, b_in, xp, 256, 256, 0, 0, 0, 1);
    // 4. depthwise conv + LN + GELU -> t
    k_dw<<<NPIX, 256>>>(dw_w, dw_b, ln_g, ln_b);
    // 5. offset & mask projections
    k_gemm<<<dim3(3, 256), 256>>>(t, w_off,  b_off,  off, 144, 256, 0, 0, 0, 0);
    k_gemm<<<dim3(2, 256), 256>>>(t, w_mask, b_mask, msk,  72, 256, 0, 0, 0, 0);
    // 6. deformable sampling + softmax-mask aggregation -> y
    k_sample<<<NPIX, 256>>>();
    // 7. output projection
    k_gemm<<<dim3(4, 256), 256>>>(y, w_out, b_out, y2, 256, 256, 0, 0, 0, 0);
    // 8. GN1 + SiLU
    k_gn<<<128, 256>>>(y2, y, gn1_g, gn1_b, 4096, 1, 0, 64);
    // 9. conv1 3x3 (implicit im2col GEMM, K=2304)
    k_gemm<<<dim3(4, 256), 256>>>(y, c1_w, c1_b, y2, 256, 2304, 1, 6, 1, 0);
    // 10. GN2 + SiLU
    k_gn<<<128, 256>>>(y2, y, gn2_g, gn2_b, 4096, 1, 0, 64);
    // 11. down conv 3x3 stride2
    k_gemm<<<dim3(4, 64), 256>>>(y, dn_w, dn_b, dn, 256, 2304, 1, 5, 2, 0);
    // 12. GN3 (no SiLU) -> NCHW output
    k_gn<<<128, 256>>>(dn, (float*)d_out, gn3_g, gn3_b, 1024, 0, 1, 32);
}

// round 3
// speedup vs baseline: 1.4316x; 1.4316x over previous
#include <cuda_runtime.h>
#include <cuda_bf16.h>
#include <cstdint>
#include <math.h>

#define NB   4
#define CC   256
#define HP   66
#define LPIX 4096
#define NPIX 16384

// ======================= PTX helpers ========================================
__device__ __forceinline__ uint32_t smem_u32(const void* p) {
    uint32_t a;
    asm("{ .reg .u64 t; cvta.to.shared.u64 t, %1; cvt.u32.u64 %0, t; }" : "=r"(a) : "l"(p));
    return a;
}
#define CP_ASYNC8(dst, src, sz) \
    asm volatile("cp.async.ca.shared.global [%0], [%1], 8, %2;" \
                 :: "r"(dst), "l"(src), "r"(sz) : "memory")
#define CP_COMMIT() asm volatile("cp.async.commit_group;" ::: "memory")
#define CP_WAIT(n)  asm volatile("cp.async.wait_group %0;" :: "n"(n) : "memory")

#define MMA_BF16(acc, A, B) \
    asm volatile("mma.sync.aligned.m16n8k16.row.col.f32.bf16.bf16.f32 " \
        "{%0,%1,%2,%3}, {%4,%5,%6,%7}, {%8,%9}, {%0,%1,%2,%3};" \
        : "+f"((acc)[0]), "+f"((acc)[1]), "+f"((acc)[2]), "+f"((acc)[3]) \
        : "r"((A)[0]), "r"((A)[1]), "r"((A)[2]), "r"((A)[3]), \
          "r"((B)[0]), "r"((B)[1]))

__device__ __forceinline__ void bsplit(float v, __nv_bfloat16& h, __nv_bfloat16& l) {
    h = __float2bfloat16(v);
    l = __float2bfloat16(v - __bfloat162float(h));
}

// ======================= scratch ============================================
__device__ float         g_xs [NPIX * CC];
__device__ __nv_bfloat16 g_xsh[NPIX * CC], g_xsl[NPIX * CC];
__device__ float         g_xp [NB * HP * HP * CC];
__device__ __nv_bfloat16 g_th [NPIX * CC], g_tl [NPIX * CC];
__device__ float         g_off[NPIX * 144];
__device__ float         g_msk[NPIX * 72];
__device__ __nv_bfloat16 g_yh [NPIX * CC], g_yl [NPIX * CC];
__device__ float         g_y2 [NPIX * CC];
__device__ __nv_bfloat16 g_gh [NPIX * CC], g_gl [NPIX * CC];
__device__ float         g_dn [NB * 32 * 32 * CC];
// weights: [N, K] bf16 hi/lo
__device__ __nv_bfloat16 g_winh[256*256],  g_winl[256*256];
__device__ __nv_bfloat16 g_wofh[144*256],  g_wofl[144*256];
__device__ __nv_bfloat16 g_wmkh[72*256],   g_wmkl[72*256];
__device__ __nv_bfloat16 g_wouh[256*256],  g_woul[256*256];
__device__ __nv_bfloat16 g_c1h[256*2304],  g_c1l[256*2304];
__device__ __nv_bfloat16 g_dwh[256*2304],  g_dwl[256*2304];

// ======================= misc kernels =======================================
__device__ __forceinline__ void block_reduce2(float &a, float &b, float* sh) {
    int lane = threadIdx.x & 31, wid = threadIdx.x >> 5;
#pragma unroll
    for (int o = 16; o; o >>= 1) {
        a += __shfl_down_sync(0xffffffffu, a, o);
        b += __shfl_down_sync(0xffffffffu, b, o);
    }
    if (lane == 0) { sh[wid] = a; sh[8 + wid] = b; }
    __syncthreads();
    if (wid == 0) {
        a = (lane < 8) ? sh[lane] : 0.f;
        b = (lane < 8) ? sh[8 + lane] : 0.f;
#pragma unroll
        for (int o = 4; o; o >>= 1) {
            a += __shfl_down_sync(0xffffffffu, a, o);
            b += __shfl_down_sync(0xffffffffu, b, o);
        }
        if (lane == 0) { sh[16] = a; sh[17] = b; }
    }
    __syncthreads();
    a = sh[16]; b = sh[17];
}

__global__ void k_transpose(const float* __restrict__ x) {
    __shared__ float tile[32][33];
    int n  = blockIdx.z;
    int c0 = blockIdx.x * 32;
    int p0 = blockIdx.y * 32;
    int tx = threadIdx.x, ty = threadIdx.y;
#pragma unroll
    for (int j = 0; j < 32; j += 8)
        tile[ty + j][tx] = x[(size_t)(n * CC + c0 + ty + j) * LPIX + p0 + tx];
    __syncthreads();
#pragma unroll
    for (int j = 0; j < 32; j += 8) {
        float v = tile[tx][ty + j];
        size_t o = (size_t)(n * LPIX + p0 + ty + j) * CC + c0 + tx;
        g_xs[o] = v;
        __nv_bfloat16 h, l; bsplit(v, h, l);
        g_xsh[o] = h; g_xsl[o] = l;
    }
}

__global__ void k_zero_xp() {
    int i = blockIdx.x * blockDim.x + threadIdx.x;
    const int total4 = (NB * HP * HP * CC) / 4;
    if (i < total4)
        reinterpret_cast<float4*>(g_xp)[i] = make_float4(0.f, 0.f, 0.f, 0.f);
}

// weight prep: w [K,N] fp32 -> Wh/Wl [N,K] bf16
__global__ void k_wprep(const float* __restrict__ w, __nv_bfloat16* __restrict__ Wh,
                        __nv_bfloat16* __restrict__ Wl, int K, int N) {
    int i = blockIdx.x * 256 + threadIdx.x;
    if (i >= K * N) return;
    int k = i / N, n = i - k * N;
    __nv_bfloat16 h, l; bsplit(w[i], h, l);
    Wh[(size_t)n * K + k] = h;
    Wl[(size_t)n * K + k] = l;
}

__global__ void k_dw(const float* __restrict__ dww, const float* __restrict__ dwb,
                     const float* __restrict__ lng, const float* __restrict__ lnb)
{
    int pix = blockIdx.x;
    int c   = threadIdx.x;
    int n = pix >> 12, h = (pix >> 6) & 63, w = pix & 63;
    float acc = dwb[c];
#pragma unroll
    for (int kh = 0; kh < 3; kh++) {
        int y = h + kh - 1;
        if ((unsigned)y >= 64u) continue;
#pragma unroll
        for (int kw = 0; kw < 3; kw++) {
            int x = w + kw - 1;
            if ((unsigned)x >= 64u) continue;
            acc += g_xs[((size_t)((n * 64 + y) * 64 + x)) * 256 + c] *
                   dww[(kh * 3 + kw) * 256 + c];
        }
    }
    __shared__ float sh[32];
    float s = acc, ss = acc * acc;
    block_reduce2(s, ss, sh);
    float mean = s * (1.f / 256.f);
    float var  = ss * (1.f / 256.f) - mean * mean;
    float rstd = rsqrtf(var + 1e-5f);
    float v = (acc - mean) * rstd * lng[c] + lnb[c];
    v = 0.5f * v * (1.f + erff(v * 0.70710678118654752440f));
    __nv_bfloat16 hh, ll; bsplit(v, hh, ll);
    g_th[(size_t)pix * 256 + c] = hh;
    g_tl[(size_t)pix * 256 + c] = ll;
}

__global__ void k_sample()
{
    int pix  = blockIdx.x;
    int g    = threadIdx.x >> 5;
    int lane = threadIdx.x & 31;
    int n = pix >> 12, h = (pix >> 6) & 63, w = pix & 63;

    const float* ml = g_msk + (size_t)pix * 72 + g * 9;
    float e[9], mx = -1e30f, s = 0.f;
#pragma unroll
    for (int p = 0; p < 9; p++) mx = fmaxf(mx, ml[p]);
#pragma unroll
    for (int p = 0; p < 9; p++) { e[p] = expf(ml[p] - mx); s += e[p]; }
    float inv = 1.f / s;

    const float* off = g_off + (size_t)pix * 144 + g * 18;
    const float* img = g_xp + (size_t)n * HP * HP * CC + g * 32 + lane;
    float acc = 0.f;
#pragma unroll
    for (int p = 0; p < 9; p++) {
        float px = (float)(w + p / 3) + off[2 * p];
        float py = (float)(h + p % 3) + off[2 * p + 1];
        float wgt = e[p] * inv;
        float x0f = floorf(px), y0f = floorf(py);
        int x0 = (int)x0f, y0 = (int)y0f;
        float fx = px - x0f, fy = py - y0f;
#pragma unroll
        for (int dy = 0; dy < 2; dy++) {
            int yy = y0 + dy;
            if ((unsigned)yy >= (unsigned)HP) continue;
            float wy = dy ? fy : 1.f - fy;
#pragma unroll
            for (int dx = 0; dx < 2; dx++) {
                int xx = x0 + dx;
                if ((unsigned)xx >= (unsigned)HP) continue;
                float wx = dx ? fx : 1.f - fx;
                acc += img[((size_t)yy * HP + xx) * CC] * (wx * wy * wgt);
            }
        }
    }
    __nv_bfloat16 hh, ll; bsplit(acc, hh, ll);
    g_yh[(size_t)pix * 256 + g * 32 + lane] = hh;
    g_yl[(size_t)pix * 256 + g * 32 + lane] = ll;
}

// GroupNorm(32) [+SiLU]; outputs optional fp32 (maybe NCHW) and/or bf16 split
__global__ void k_gn(const float* __restrict__ in, float* __restrict__ outf,
                     __nv_bfloat16* __restrict__ oh, __nv_bfloat16* __restrict__ ol,
                     const float* __restrict__ gamma, const float* __restrict__ beta,
                     int HWn, int do_silu, int out_nchw, int Wd)
{
    int n = blockIdx.x >> 5;
    int g = blockIdx.x & 31;
    int cnt = HWn * 8;
    const float* base = in + (size_t)n * HWn * 256 + g * 8;
    float s = 0.f, ss = 0.f;
    for (int i = threadIdx.x; i < cnt; i += 256) {
        float v = base[(size_t)(i >> 3) * 256 + (i & 7)];
        s += v; ss += v * v;
    }
    __shared__ float sh[32];
    block_reduce2(s, ss, sh);
    float mean = s / (float)cnt;
    float rstd = rsqrtf(ss / (float)cnt - mean * mean + 1e-5f);
    for (int i = threadIdx.x; i < cnt; i += 256) {
        int l = i >> 3, c = i & 7;
        float v = base[(size_t)l * 256 + c];
        v = (v - mean) * rstd * gamma[g * 8 + c] + beta[g * 8 + c];
        if (do_silu) v = v * (1.f / (1.f + expf(-v)));
        if (outf) {
            if (out_nchw)
                outf[(((size_t)n * 256 + g * 8 + c) * Wd + (l / Wd)) * Wd + (l % Wd)] = v;
            else
                outf[((size_t)n * HWn + l) * 256 + g * 8 + c] = v;
        }
        if (oh) {
            __nv_bfloat16 hh, ll; bsplit(v, hh, ll);
            size_t o = ((size_t)n * HWn + l) * 256 + g * 8 + c;
            oh[o] = hh; ol[o] = ll;
        }
    }
}

// ======================= mma.sync split-bf16 GEMM ============================
// C[M,N] = A[M,K]*B[K,N] + bias  via Ah*Bh + Ah*Bl + Al*Bh  (HMMA, fp32 acc)
// A: bf16 hi/lo [M,256-chunk layout]; mode0 direct, mode1 implicit im2col
// B: bf16 hi/lo [N,K] row-major. CTA tile 128x128, BK=32, 8 warps (2m x 4n).
#define PITCH  72
#define MATB   9216              // 128 * 72
#define STAGE  36864             // 4 * MATB
#define SM_TOT 73728             // 2 stages

__global__ void __launch_bounds__(256, 1)
k_mma(const __nv_bfloat16* __restrict__ Ah, const __nv_bfloat16* __restrict__ Al,
      const __nv_bfloat16* __restrict__ Bh, const __nv_bfloat16* __restrict__ Bl,
      const float* __restrict__ bias, float* __restrict__ Cout,
      int N, int K, int mode, int owbits, int stride, int padout)
{
    extern __shared__ __align__(16) char smem[];
    const uint32_t sb = smem_u32(smem);
    const int tid = threadIdx.x;
    const int wid = tid >> 5, lane = tid & 31;
    const int g = lane >> 2, tg = lane & 3;
    const int warpM = wid & 1, warpN = wid >> 1;
    const int m0 = blockIdx.x * 128;
    const int n0 = blockIdx.y * 128;
    const int S = K >> 5;

    float acc[4][4][4];
#pragma unroll
    for (int i = 0; i < 4; i++)
#pragma unroll
        for (int j = 0; j < 4; j++)
#pragma unroll
            for (int r = 0; r < 4; r++) acc[i][j][r] = 0.f;

    auto fill = [&](int s, int buf) {
        int k0 = s << 5;
        int tap = k0 >> 8, ci0 = k0 & 255;
        int kh = tap / 3, kw = tap - 3 * kh;
#pragma unroll 4
        for (int cid = tid; cid < 4096; cid += 256) {
            int mat = cid >> 10;
            int row = (cid >> 3) & 127;
            int ch  = cid & 7;
            uint32_t dst = sb + buf * STAGE + mat * MATB + row * PITCH + ch * 8;
            const __nv_bfloat16* src;
            int sz = 8;
            if (mat < 2) {
                const __nv_bfloat16* Ag = mat ? Al : Ah;
                int m = m0 + row;
                if (mode == 0) {
                    src = Ag + (size_t)m * K + k0 + ch * 4;
                } else {
                    int nn = m >> (2 * owbits);
                    int hw = m & ((1 << (2 * owbits)) - 1);
                    int ohh = hw >> owbits, oww = hw & ((1 << owbits) - 1);
                    int iy = ohh * stride + kh - 1, ix = oww * stride + kw - 1;
                    if ((unsigned)iy < 64u && (unsigned)ix < 64u)
                        src = Ag + ((size_t)((nn * 64 + iy) * 64 + ix)) * 256 + ci0 + ch * 4;
                    else { src = Ag; sz = 0; }
                }
            } else {
                const __nv_bfloat16* Bg = (mat == 3) ? Bl : Bh;
                int n = n0 + row;
                if (n < N) src = Bg + (size_t)n * K + k0 + ch * 4;
                else { src = Bg; sz = 0; }
            }
            CP_ASYNC8(dst, src, sz);
        }
    };

    auto compute = [&](int buf) {
        const char* st = smem + buf * STAGE;
#pragma unroll
        for (int kk = 0; kk < 2; kk++) {
            int cb = kk * 32 + tg * 4;
            uint32_t ah[4][4], al_[4][4], bh[4][2], bl_[4][2];
#pragma unroll
            for (int mi = 0; mi < 4; mi++) {
                int r0 = warpM * 64 + mi * 16 + g;
                const char* pah = st + (size_t)r0 * PITCH + cb;
                const char* pal = st + MATB + (size_t)r0 * PITCH + cb;
                ah[mi][0] = *reinterpret_cast<const uint32_t*>(pah);
                ah[mi][1] = *reinterpret_cast<const uint32_t*>(pah + 8 * PITCH);
                ah[mi][2] = *reinterpret_cast<const uint32_t*>(pah + 16);
                ah[mi][3] = *reinterpret_cast<const uint32_t*>(pah + 8 * PITCH + 16);
                al_[mi][0] = *reinterpret_cast<const uint32_t*>(pal);
                al_[mi][1] = *reinterpret_cast<const uint32_t*>(pal + 8 * PITCH);
                al_[mi][2] = *reinterpret_cast<const uint32_t*>(pal + 16);
                al_[mi][3] = *reinterpret_cast<const uint32_t*>(pal + 8 * PITCH + 16);
            }
#pragma unroll
            for (int ni = 0; ni < 4; ni++) {
                int rn = warpN * 32 + ni * 8 + g;
                const char* pbh = st + 2 * MATB + (size_t)rn * PITCH + cb;
                const char* pbl = st + 3 * MATB + (size_t)rn * PITCH + cb;
                bh[ni][0] = *reinterpret_cast<const uint32_t*>(pbh);
                bh[ni][1] = *reinterpret_cast<const uint32_t*>(pbh + 16);
                bl_[ni][0] = *reinterpret_cast<const uint32_t*>(pbl);
                bl_[ni][1] = *reinterpret_cast<const uint32_t*>(pbl + 16);
            }
#pragma unroll
            for (int mi = 0; mi < 4; mi++)
#pragma unroll
                for (int ni = 0; ni < 4; ni++) {
                    MMA_BF16(acc[mi][ni], ah[mi], bh[ni]);
                    MMA_BF16(acc[mi][ni], ah[mi], bl_[ni]);
                    MMA_BF16(acc[mi][ni], al_[mi], bh[ni]);
                }
        }
    };

    fill(0, 0); CP_COMMIT();
    for (int s = 0; s < S; s++) {
        int b = s & 1;
        if (s + 1 < S) { fill(s + 1, b ^ 1); CP_COMMIT(); CP_WAIT(1); }
        else           { CP_WAIT(0); }
        __syncthreads();
        compute(b);
        __syncthreads();
    }

    // ---- epilogue ----
#pragma unroll
    for (int mi = 0; mi < 4; mi++) {
        int mA = m0 + warpM * 64 + mi * 16 + g;
#pragma unroll
        for (int half = 0; half < 2; half++) {
            int m = mA + half * 8;
            float* orow;
            if (padout) {
                int n = m >> 12, h = (m >> 6) & 63, w = m & 63;
                orow = Cout + ((size_t)(n * HP + h + 1) * HP + (w + 1)) * 256;
            } else {
                orow = Cout + (size_t)m * N;
            }
#pragma unroll
            for (int ni = 0; ni < 4; ni++) {
                int nc = n0 + warpN * 32 + ni * 8 + tg * 2;
                if (nc < N)     orow[nc]     = acc[mi][ni][half * 2]     + bias[nc];
                if (nc + 1 < N) orow[nc + 1] = acc[mi][ni][half * 2 + 1] + bias[nc + 1];
            }
        }
    }
}

// ======================= launch =============================================
extern "C" void kernel_launch(void* const* d_in, const int* in_sizes, int n_in,
                              void* d_out, int out_size)
{
    const float* x      = (const float*)d_in[0];
    const float* w_in   = (const float*)d_in[1];
    const float* b_in   = (const float*)d_in[2];
    const float* dw_w   = (const float*)d_in[3];
    const float* dw_b   = (const float*)d_in[4];
    const float* ln_g   = (const float*)d_in[5];
    const float* ln_b   = (const float*)d_in[6];
    const float* w_off  = (const float*)d_in[7];
    const float* b_off  = (const float*)d_in[8];
    const float* w_mask = (const float*)d_in[9];
    const float* b_mask = (const float*)d_in[10];
    const float* w_out  = (const float*)d_in[11];
    const float* b_out  = (const float*)d_in[12];
    const float* gn1_g  = (const float*)d_in[13];
    const float* gn1_b  = (const float*)d_in[14];
    const float* c1_w   = (const float*)d_in[15];
    const float* c1_b   = (const float*)d_in[16];
    const float* gn2_g  = (const float*)d_in[17];
    const float* gn2_b  = (const float*)d_in[18];
    const float* dn_w   = (const float*)d_in[19];
    const float* dn_b   = (const float*)d_in[20];
    const float* gn3_g  = (const float*)d_in[21];
    const float* gn3_b  = (const float*)d_in[22];

    cudaFuncSetAttribute(k_mma, cudaFuncAttributeMaxDynamicSharedMemorySize, SM_TOT);

    float *xp, *off, *msk, *y2, *dn;
    __nv_bfloat16 *xsh, *xsl, *th, *tl, *yh, *yl, *gh, *gl;
    __nv_bfloat16 *winh,*winl,*wofh,*wofl,*wmkh,*wmkl,*wouh,*woul,*c1h,*c1l,*dwh,*dwl;
    cudaGetSymbolAddress((void**)&xp,  g_xp);
    cudaGetSymbolAddress((void**)&off, g_off);
    cudaGetSymbolAddress((void**)&msk, g_msk);
    cudaGetSymbolAddress((void**)&y2,  g_y2);
    cudaGetSymbolAddress((void**)&dn,  g_dn);
    cudaGetSymbolAddress((void**)&xsh, g_xsh); cudaGetSymbolAddress((void**)&xsl, g_xsl);
    cudaGetSymbolAddress((void**)&th,  g_th);  cudaGetSymbolAddress((void**)&tl,  g_tl);
    cudaGetSymbolAddress((void**)&yh,  g_yh);  cudaGetSymbolAddress((void**)&yl,  g_yl);
    cudaGetSymbolAddress((void**)&gh,  g_gh);  cudaGetSymbolAddress((void**)&gl,  g_gl);
    cudaGetSymbolAddress((void**)&winh, g_winh); cudaGetSymbolAddress((void**)&winl, g_winl);
    cudaGetSymbolAddress((void**)&wofh, g_wofh); cudaGetSymbolAddress((void**)&wofl, g_wofl);
    cudaGetSymbolAddress((void**)&wmkh, g_wmkh); cudaGetSymbolAddress((void**)&wmkl, g_wmkl);
    cudaGetSymbolAddress((void**)&wouh, g_wouh); cudaGetSymbolAddress((void**)&woul, g_woul);
    cudaGetSymbolAddress((void**)&c1h,  g_c1h);  cudaGetSymbolAddress((void**)&c1l,  g_c1l);
    cudaGetSymbolAddress((void**)&dwh,  g_dwh);  cudaGetSymbolAddress((void**)&dwl,  g_dwl);

    // weight prep
    k_wprep<<<(256*256 + 255) / 256, 256>>>(w_in,   winh, winl, 256, 256);
    k_wprep<<<(256*144 + 255) / 256, 256>>>(w_off,  wofh, wofl, 256, 144);
    k_wprep<<<(256*72  + 255) / 256, 256>>>(w_mask, wmkh, wmkl, 256, 72);
    k_wprep<<<(256*256 + 255) / 256, 256>>>(w_out,  wouh, woul, 256, 256);
    k_wprep<<<(2304*256 + 255) / 256, 256>>>(c1_w,  c1h,  c1l,  2304, 256);
    k_wprep<<<(2304*256 + 255) / 256, 256>>>(dn_w,  dwh,  dwl,  2304, 256);

    // 1. NCHW -> NHWC (+ bf16 split)
    k_transpose<<<dim3(8, 128, 4), dim3(32, 8)>>>(x);
    // 2. zero padded buffer
    k_zero_xp<<<(NB * HP * HP * CC / 4 + 255) / 256, 256>>>();
    // 3. input projection -> padded xp (fp32)
    k_mma<<<dim3(128, 2), 256, SM_TOT>>>(xsh, xsl, winh, winl, b_in, xp, 256, 256, 0, 0, 0, 1);
    // 4. depthwise + LN + GELU -> t (bf16 split)
    k_dw<<<NPIX, 256>>>(dw_w, dw_b, ln_g, ln_b);
    // 5. offset & mask projections
    k_mma<<<dim3(128, 2), 256, SM_TOT>>>(th, tl, wofh, wofl, b_off,  off, 144, 256, 0, 0, 0, 0);
    k_mma<<<dim3(128, 1), 256, SM_TOT>>>(th, tl, wmkh, wmkl, b_mask, msk,  72, 256, 0, 0, 0, 0);
    // 6. deformable sampling -> y (bf16 split)
    k_sample<<<NPIX, 256>>>();
    // 7. output projection -> y2 (fp32)
    k_mma<<<dim3(128, 2), 256, SM_TOT>>>(yh, yl, wouh, woul, b_out, y2, 256, 256, 0, 0, 0, 0);
    // 8. GN1 + SiLU -> bf16 split
    k_gn<<<128, 256>>>(y2, (float*)nullptr, gh, gl, gn1_g, gn1_b, 4096, 1, 0, 64);
    // 9. conv1 3x3 implicit im2col (K=2304) -> y2
    k_mma<<<dim3(128, 2), 256, SM_TOT>>>(gh, gl, c1h, c1l, c1_b, y2, 256, 2304, 1, 6, 1, 0);
    // 10. GN2 + SiLU -> bf16 split
    k_gn<<<128, 256>>>(y2, (float*)nullptr, gh, gl, gn2_g, gn2_b, 4096, 1, 0, 64);
    // 11. down conv 3x3 stride2 (M=4096) -> dn
    k_mma<<<dim3(32, 2), 256, SM_TOT>>>(gh, gl, dwh, dwl, dn_b, dn, 256, 2304, 1, 5, 2, 0);
    // 12. GN3 -> NCHW output
    k_gn<<<128, 256>>>(dn, (float*)d_out, (__nv_bfloat16*)nullptr, (__nv_bfloat16*)nullptr,
                       gn3_g, gn3_b, 1024, 0, 1, 32);
}

// round 4
// speedup vs baseline: 2.0186x; 1.4100x over previous
#include <cuda_runtime.h>
#include <cuda_bf16.h>
#include <cstdint>
#include <math.h>

#define NB   4
#define CC   256
#define HP   66
#define LPIX 4096
#define NPIX 16384

// ======================= PTX helpers ========================================
__device__ __forceinline__ uint32_t smem_u32(const void* p) {
    uint32_t a;
    asm("{ .reg .u64 t; cvta.to.shared.u64 t, %1; cvt.u32.u64 %0, t; }" : "=r"(a) : "l"(p));
    return a;
}
#define CP_ASYNC16(dst, src, sz) \
    asm volatile("cp.async.cg.shared.global [%0], [%1], 16, %2;" \
                 :: "r"(dst), "l"(src), "r"(sz) : "memory")
#define CP_COMMIT() asm volatile("cp.async.commit_group;" ::: "memory")
#define CP_WAIT(n)  asm volatile("cp.async.wait_group %0;" :: "n"(n) : "memory")

#define LDSM4(r0, r1, r2, r3, a) \
    asm volatile("ldmatrix.sync.aligned.m8n8.x4.shared.b16 {%0,%1,%2,%3}, [%4];" \
        : "=r"(r0), "=r"(r1), "=r"(r2), "=r"(r3) : "r"(a))

#define MMA_BF16(acc, A, B) \
    asm volatile("mma.sync.aligned.m16n8k16.row.col.f32.bf16.bf16.f32 " \
        "{%0,%1,%2,%3}, {%4,%5,%6,%7}, {%8,%9}, {%0,%1,%2,%3};" \
        : "+f"((acc)[0]), "+f"((acc)[1]), "+f"((acc)[2]), "+f"((acc)[3]) \
        : "r"((A)[0]), "r"((A)[1]), "r"((A)[2]), "r"((A)[3]), \
          "r"((B)[0]), "r"((B)[1]))

__device__ __forceinline__ void bsplit(float v, __nv_bfloat16& h, __nv_bfloat16& l) {
    h = __float2bfloat16(v);
    l = __float2bfloat16(v - __bfloat162float(h));
}

// ======================= scratch ============================================
__device__ float         g_xs [NPIX * CC];
__device__ __nv_bfloat16 g_xsh[NPIX * CC], g_xsl[NPIX * CC];
__device__ float         g_xp [NB * HP * HP * CC];
__device__ __nv_bfloat16 g_th [NPIX * CC], g_tl [NPIX * CC];
__device__ float         g_off[NPIX * 144];
__device__ float         g_msk[NPIX * 72];
__device__ __nv_bfloat16 g_yh [NPIX * CC], g_yl [NPIX * CC];
__device__ float         g_y2 [NPIX * CC];
__device__ __nv_bfloat16 g_gh [NPIX * CC], g_gl [NPIX * CC];
__device__ float         g_dn [NB * 32 * 32 * CC];
// weights: [N, K] bf16 hi/lo
__device__ __nv_bfloat16 g_winh[256*256],  g_winl[256*256];
__device__ __nv_bfloat16 g_wofh[144*256],  g_wofl[144*256];
__device__ __nv_bfloat16 g_wmkh[72*256],   g_wmkl[72*256];
__device__ __nv_bfloat16 g_wouh[256*256],  g_woul[256*256];
__device__ __nv_bfloat16 g_c1h[256*2304],  g_c1l[256*2304];
__device__ __nv_bfloat16 g_dwh[256*2304],  g_dwl[256*2304];

// ======================= misc kernels =======================================
__device__ __forceinline__ void block_reduce2(float &a, float &b, float* sh) {
    int lane = threadIdx.x & 31, wid = threadIdx.x >> 5;
#pragma unroll
    for (int o = 16; o; o >>= 1) {
        a += __shfl_down_sync(0xffffffffu, a, o);
        b += __shfl_down_sync(0xffffffffu, b, o);
    }
    if (lane == 0) { sh[wid] = a; sh[8 + wid] = b; }
    __syncthreads();
    if (wid == 0) {
        a = (lane < 8) ? sh[lane] : 0.f;
        b = (lane < 8) ? sh[8 + lane] : 0.f;
#pragma unroll
        for (int o = 4; o; o >>= 1) {
            a += __shfl_down_sync(0xffffffffu, a, o);
            b += __shfl_down_sync(0xffffffffu, b, o);
        }
        if (lane == 0) { sh[16] = a; sh[17] = b; }
    }
    __syncthreads();
    a = sh[16]; b = sh[17];
}

__global__ void k_transpose(const float* __restrict__ x) {
    __shared__ float tile[32][33];
    int n  = blockIdx.z;
    int c0 = blockIdx.x * 32;
    int p0 = blockIdx.y * 32;
    int tx = threadIdx.x, ty = threadIdx.y;
#pragma unroll
    for (int j = 0; j < 32; j += 8)
        tile[ty + j][tx] = x[(size_t)(n * CC + c0 + ty + j) * LPIX + p0 + tx];
    __syncthreads();
#pragma unroll
    for (int j = 0; j < 32; j += 8) {
        float v = tile[tx][ty + j];
        size_t o = (size_t)(n * LPIX + p0 + ty + j) * CC + c0 + tx;
        g_xs[o] = v;
        __nv_bfloat16 h, l; bsplit(v, h, l);
        g_xsh[o] = h; g_xsl[o] = l;
    }
}

__global__ void k_zero_xp() {
    int i = blockIdx.x * blockDim.x + threadIdx.x;
    const int total4 = (NB * HP * HP * CC) / 4;
    if (i < total4)
        reinterpret_cast<float4*>(g_xp)[i] = make_float4(0.f, 0.f, 0.f, 0.f);
}

// weight prep: w [K,N] fp32 -> Wh/Wl [N,K] bf16
__global__ void k_wprep(const float* __restrict__ w, __nv_bfloat16* __restrict__ Wh,
                        __nv_bfloat16* __restrict__ Wl, int K, int N) {
    int i = blockIdx.x * 256 + threadIdx.x;
    if (i >= K * N) return;
    int k = i / N, n = i - k * N;
    __nv_bfloat16 h, l; bsplit(w[i], h, l);
    Wh[(size_t)n * K + k] = h;
    Wl[(size_t)n * K + k] = l;
}

__global__ void k_dw(const float* __restrict__ dww, const float* __restrict__ dwb,
                     const float* __restrict__ lng, const float* __restrict__ lnb)
{
    int pix = blockIdx.x;
    int c   = threadIdx.x;
    int n = pix >> 12, h = (pix >> 6) & 63, w = pix & 63;
    float acc = dwb[c];
#pragma unroll
    for (int kh = 0; kh < 3; kh++) {
        int y = h + kh - 1;
        if ((unsigned)y >= 64u) continue;
#pragma unroll
        for (int kw = 0; kw < 3; kw++) {
            int x = w + kw - 1;
            if ((unsigned)x >= 64u) continue;
            acc += g_xs[((size_t)((n * 64 + y) * 64 + x)) * 256 + c] *
                   dww[(kh * 3 + kw) * 256 + c];
        }
    }
    __shared__ float sh[32];
    float s = acc, ss = acc * acc;
    block_reduce2(s, ss, sh);
    float mean = s * (1.f / 256.f);
    float var  = ss * (1.f / 256.f) - mean * mean;
    float rstd = rsqrtf(var + 1e-5f);
    float v = (acc - mean) * rstd * lng[c] + lnb[c];
    v = 0.5f * v * (1.f + erff(v * 0.70710678118654752440f));
    __nv_bfloat16 hh, ll; bsplit(v, hh, ll);
    g_th[(size_t)pix * 256 + c] = hh;
    g_tl[(size_t)pix * 256 + c] = ll;
}

__global__ void k_sample()
{
    int pix  = blockIdx.x;
    int g    = threadIdx.x >> 5;
    int lane = threadIdx.x & 31;
    int n = pix >> 12, h = (pix >> 6) & 63, w = pix & 63;

    const float* ml = g_msk + (size_t)pix * 72 + g * 9;
    float e[9], mx = -1e30f, s = 0.f;
#pragma unroll
    for (int p = 0; p < 9; p++) mx = fmaxf(mx, ml[p]);
#pragma unroll
    for (int p = 0; p < 9; p++) { e[p] = expf(ml[p] - mx); s += e[p]; }
    float inv = 1.f / s;

    const float* off = g_off + (size_t)pix * 144 + g * 18;
    const float* img = g_xp + (size_t)n * HP * HP * CC + g * 32 + lane;
    float acc = 0.f;
#pragma unroll
    for (int p = 0; p < 9; p++) {
        float px = (float)(w + p / 3) + off[2 * p];
        float py = (float)(h + p % 3) + off[2 * p + 1];
        float wgt = e[p] * inv;
        float x0f = floorf(px), y0f = floorf(py);
        int x0 = (int)x0f, y0 = (int)y0f;
        float fx = px - x0f, fy = py - y0f;
#pragma unroll
        for (int dy = 0; dy < 2; dy++) {
            int yy = y0 + dy;
            if ((unsigned)yy >= (unsigned)HP) continue;
            float wy = dy ? fy : 1.f - fy;
#pragma unroll
            for (int dx = 0; dx < 2; dx++) {
                int xx = x0 + dx;
                if ((unsigned)xx >= (unsigned)HP) continue;
                float wx = dx ? fx : 1.f - fx;
                acc += img[((size_t)yy * HP + xx) * CC] * (wx * wy * wgt);
            }
        }
    }
    __nv_bfloat16 hh, ll; bsplit(acc, hh, ll);
    g_yh[(size_t)pix * 256 + g * 32 + lane] = hh;
    g_yl[(size_t)pix * 256 + g * 32 + lane] = ll;
}

// GroupNorm(32) [+SiLU]; outputs optional fp32 (maybe NCHW) and/or bf16 split
__global__ void k_gn(const float* __restrict__ in, float* __restrict__ outf,
                     __nv_bfloat16* __restrict__ oh, __nv_bfloat16* __restrict__ ol,
                     const float* __restrict__ gamma, const float* __restrict__ beta,
                     int HWn, int do_silu, int out_nchw, int Wd)
{
    int n = blockIdx.x >> 5;
    int g = blockIdx.x & 31;
    int cnt = HWn * 8;
    const float* base = in + (size_t)n * HWn * 256 + g * 8;
    float s = 0.f, ss = 0.f;
    for (int i = threadIdx.x; i < cnt; i += 256) {
        float v = base[(size_t)(i >> 3) * 256 + (i & 7)];
        s += v; ss += v * v;
    }
    __shared__ float sh[32];
    block_reduce2(s, ss, sh);
    float mean = s / (float)cnt;
    float rstd = rsqrtf(ss / (float)cnt - mean * mean + 1e-5f);
    for (int i = threadIdx.x; i < cnt; i += 256) {
        int l = i >> 3, c = i & 7;
        float v = base[(size_t)l * 256 + c];
        v = (v - mean) * rstd * gamma[g * 8 + c] + beta[g * 8 + c];
        if (do_silu) v = v * (1.f / (1.f + expf(-v)));
        if (outf) {
            if (out_nchw)
                outf[(((size_t)n * 256 + g * 8 + c) * Wd + (l / Wd)) * Wd + (l % Wd)] = v;
            else
                outf[((size_t)n * HWn + l) * 256 + g * 8 + c] = v;
        }
        if (oh) {
            __nv_bfloat16 hh, ll; bsplit(v, hh, ll);
            size_t o = ((size_t)n * HWn + l) * 256 + g * 8 + c;
            oh[o] = hh; ol[o] = ll;
        }
    }
}

// ======================= mma.sync split-bf16 GEMM ============================
// C[M,N] = A[M,K]*B[K,N] + bias  via Ah*Bh + Ah*Bl + Al*Bh  (HMMA, fp32 acc)
// BK=64, 3-stage cp.async pipeline, ldmatrix + SW128-style XOR swizzle.
// smem per stage: 4 matrices (Ah,Al,Bh,Bl) x 128 rows x 128B = 64KB
#define MATB   16384
#define STAGE  65536
#define SM_TOT 196608

__global__ void __launch_bounds__(256, 1)
k_mma(const __nv_bfloat16* __restrict__ Ah, const __nv_bfloat16* __restrict__ Al,
      const __nv_bfloat16* __restrict__ Bh, const __nv_bfloat16* __restrict__ Bl,
      const float* __restrict__ bias, float* __restrict__ Cout,
      int N, int K, int mode, int owbits, int stride, int padout)
{
    extern __shared__ __align__(128) char smem[];
    const uint32_t sb = smem_u32(smem);
    const int tid = threadIdx.x;
    const int wid = tid >> 5, lane = tid & 31;
    const int g = lane >> 2, tg = lane & 3;
    const int warpM = wid & 1, warpN = wid >> 1;
    const int m0 = blockIdx.x * 128;
    const int n0 = blockIdx.y * 128;
    const int S = K >> 6;

    float acc[4][4][4];
#pragma unroll
    for (int i = 0; i < 4; i++)
#pragma unroll
        for (int j = 0; j < 4; j++)
#pragma unroll
            for (int r = 0; r < 4; r++) acc[i][j][r] = 0.f;

    auto fill = [&](int s, int st) {
        int k0 = s << 6;
        int tap = k0 >> 8, ci0 = k0 & 255;
        int kh = tap / 3, kw = tap - 3 * kh;
        uint32_t stbase = sb + st * STAGE;
#pragma unroll 4
        for (int q = 0; q < 16; q++) {
            int cid = q * 256 + tid;           // 0..4095
            int mat = cid >> 10;
            int idx = cid & 1023;
            int r = idx >> 3, c = idx & 7;
            uint32_t dst = stbase + mat * MATB + r * 128 + ((c ^ (r & 7)) << 4);
            const __nv_bfloat16* src;
            int sz = 16;
            if (mat < 2) {
                const __nv_bfloat16* Ag = mat ? Al : Ah;
                int m = m0 + r;
                if (mode == 0) {
                    src = Ag + (size_t)m * K + k0 + c * 8;
                } else {
                    int nn = m >> (2 * owbits);
                    int hw = m & ((1 << (2 * owbits)) - 1);
                    int ohh = hw >> owbits, oww = hw & ((1 << owbits) - 1);
                    int iy = ohh * stride + kh - 1, ix = oww * stride + kw - 1;
                    if ((unsigned)iy < 64u && (unsigned)ix < 64u)
                        src = Ag + ((size_t)((nn * 64 + iy) * 64 + ix)) * 256 + ci0 + c * 8;
                    else { src = Ag; sz = 0; }
                }
            } else {
                const __nv_bfloat16* Bg = (mat == 3) ? Bl : Bh;
                int n = n0 + r;
                if (n < N) src = Bg + (size_t)n * K + k0 + c * 8;
                else { src = Bg; sz = 0; }
            }
            CP_ASYNC16(dst, src, sz);
        }
    };

    const int lx = lane & 7;
    const uint32_t laneA_row = (uint32_t)(warpM * 64 + lx + ((lane >> 3) & 1) * 8) * 128;
    const uint32_t laneB_row = (uint32_t)(warpN * 32 + lx + ((lane >> 4) & 1) * 8) * 128;
    const int cselA = (lane >> 4) & 1;
    const int cselB = (lane >> 3) & 1;

    auto compute = [&](int st) {
        uint32_t bAh = sb + st * STAGE;
        uint32_t bAl = bAh + MATB;
        uint32_t bBh = bAh + 2 * MATB;
        uint32_t bBl = bAh + 3 * MATB;
#pragma unroll
        for (int kk = 0; kk < 4; kk++) {
            uint32_t swzA = (uint32_t)(((kk * 2 + cselA) ^ lx) << 4);
            uint32_t swzB = (uint32_t)(((kk * 2 + cselB) ^ lx) << 4);
            uint32_t ah[4][4], al_[4][4], bh[4][2], bl_[4][2];
#pragma unroll
            for (int mi = 0; mi < 4; mi++) {
                LDSM4(ah[mi][0], ah[mi][1], ah[mi][2], ah[mi][3],
                      bAh + laneA_row + mi * 2048 + swzA);
                LDSM4(al_[mi][0], al_[mi][1], al_[mi][2], al_[mi][3],
                      bAl + laneA_row + mi * 2048 + swzA);
            }
#pragma unroll
            for (int np = 0; np < 2; np++) {
                LDSM4(bh[np*2][0], bh[np*2][1], bh[np*2+1][0], bh[np*2+1][1],
                      bBh + laneB_row + np * 2048 + swzB);
                LDSM4(bl_[np*2][0], bl_[np*2][1], bl_[np*2+1][0], bl_[np*2+1][1],
                      bBl + laneB_row + np * 2048 + swzB);
            }
#pragma unroll
            for (int mi = 0; mi < 4; mi++)
#pragma unroll
                for (int ni = 0; ni < 4; ni++) {
                    MMA_BF16(acc[mi][ni], ah[mi], bh[ni]);
                    MMA_BF16(acc[mi][ni], ah[mi], bl_[ni]);
                    MMA_BF16(acc[mi][ni], al_[mi], bh[ni]);
                }
        }
    };

    // 3-stage pipeline, one barrier per stage
    fill(0, 0); CP_COMMIT();
    fill(1, 1); CP_COMMIT();
    int st = 0;
    for (int s = 0; s < S; s++) {
        CP_WAIT(1);
        __syncthreads();
        int st2 = st + 2; if (st2 >= 3) st2 -= 3;
        if (s + 2 < S) fill(s + 2, st2);
        CP_COMMIT();
        compute(st);
        if (++st == 3) st = 0;
    }

    // ---- epilogue ----
#pragma unroll
    for (int mi = 0; mi < 4; mi++) {
        int mA = m0 + warpM * 64 + mi * 16 + g;
#pragma unroll
        for (int half = 0; half < 2; half++) {
            int m = mA + half * 8;
            float* orow;
            if (padout) {
                int n = m >> 12, h = (m >> 6) & 63, w = m & 63;
                orow = Cout + ((size_t)(n * HP + h + 1) * HP + (w + 1)) * 256;
            } else {
                orow = Cout + (size_t)m * N;
            }
#pragma unroll
            for (int ni = 0; ni < 4; ni++) {
                int nc = n0 + warpN * 32 + ni * 8 + tg * 2;
                if (nc < N)     orow[nc]     = acc[mi][ni][half * 2]     + bias[nc];
                if (nc + 1 < N) orow[nc + 1] = acc[mi][ni][half * 2 + 1] + bias[nc + 1];
            }
        }
    }
}

// ======================= launch =============================================
extern "C" void kernel_launch(void* const* d_in, const int* in_sizes, int n_in,
                              void* d_out, int out_size)
{
    const float* x      = (const float*)d_in[0];
    const float* w_in   = (const float*)d_in[1];
    const float* b_in   = (const float*)d_in[2];
    const float* dw_w   = (const float*)d_in[3];
    const float* dw_b   = (const float*)d_in[4];
    const float* ln_g   = (const float*)d_in[5];
    const float* ln_b   = (const float*)d_in[6];
    const float* w_off  = (const float*)d_in[7];
    const float* b_off  = (const float*)d_in[8];
    const float* w_mask = (const float*)d_in[9];
    const float* b_mask = (const float*)d_in[10];
    const float* w_out  = (const float*)d_in[11];
    const float* b_out  = (const float*)d_in[12];
    const float* gn1_g  = (const float*)d_in[13];
    const float* gn1_b  = (const float*)d_in[14];
    const float* c1_w   = (const float*)d_in[15];
    const float* c1_b   = (const float*)d_in[16];
    const float* gn2_g  = (const float*)d_in[17];
    const float* gn2_b  = (const float*)d_in[18];
    const float* dn_w   = (const float*)d_in[19];
    const float* dn_b   = (const float*)d_in[20];
    const float* gn3_g  = (const float*)d_in[21];
    const float* gn3_b  = (const float*)d_in[22];

    cudaFuncSetAttribute(k_mma, cudaFuncAttributeMaxDynamicSharedMemorySize, SM_TOT);

    float *xp, *off, *msk, *y2, *dn;
    __nv_bfloat16 *xsh, *xsl, *th, *tl, *yh, *yl, *gh, *gl;
    __nv_bfloat16 *winh,*winl,*wofh,*wofl,*wmkh,*wmkl,*wouh,*woul,*c1h,*c1l,*dwh,*dwl;
    cudaGetSymbolAddress((void**)&xp,  g_xp);
    cudaGetSymbolAddress((void**)&off, g_off);
    cudaGetSymbolAddress((void**)&msk, g_msk);
    cudaGetSymbolAddress((void**)&y2,  g_y2);
    cudaGetSymbolAddress((void**)&dn,  g_dn);
    cudaGetSymbolAddress((void**)&xsh, g_xsh); cudaGetSymbolAddress((void**)&xsl, g_xsl);
    cudaGetSymbolAddress((void**)&th,  g_th);  cudaGetSymbolAddress((void**)&tl,  g_tl);
    cudaGetSymbolAddress((void**)&yh,  g_yh);  cudaGetSymbolAddress((void**)&yl,  g_yl);
    cudaGetSymbolAddress((void**)&gh,  g_gh);  cudaGetSymbolAddress((void**)&gl,  g_gl);
    cudaGetSymbolAddress((void**)&winh, g_winh); cudaGetSymbolAddress((void**)&winl, g_winl);
    cudaGetSymbolAddress((void**)&wofh, g_wofh); cudaGetSymbolAddress((void**)&wofl, g_wofl);
    cudaGetSymbolAddress((void**)&wmkh, g_wmkh); cudaGetSymbolAddress((void**)&wmkl, g_wmkl);
    cudaGetSymbolAddress((void**)&wouh, g_wouh); cudaGetSymbolAddress((void**)&woul, g_woul);
    cudaGetSymbolAddress((void**)&c1h,  g_c1h);  cudaGetSymbolAddress((void**)&c1l,  g_c1l);
    cudaGetSymbolAddress((void**)&dwh,  g_dwh);  cudaGetSymbolAddress((void**)&dwl,  g_dwl);

    // Launch order chosen so ncu (-s 5 -c 1) profiles the 6th launch = k_mma inproj.
    k_wprep<<<(256*256 + 255) / 256, 256>>>(w_in,   winh, winl, 256, 256);   // 0
    k_transpose<<<dim3(8, 128, 4), dim3(32, 8)>>>(x);                         // 1
    k_zero_xp<<<(NB * HP * HP * CC / 4 + 255) / 256, 256>>>();                // 2
    k_wprep<<<(2304*256 + 255) / 256, 256>>>(c1_w,  c1h,  c1l,  2304, 256);   // 3
    k_wprep<<<(2304*256 + 255) / 256, 256>>>(dn_w,  dwh,  dwl,  2304, 256);   // 4
    // 5: input projection -> padded xp (fp32)   [PROFILED LAUNCH]
    k_mma<<<dim3(128, 2), 256, SM_TOT>>>(xsh, xsl, winh, winl, b_in, xp, 256, 256, 0, 0, 0, 1);
    k_wprep<<<(256*144 + 255) / 256, 256>>>(w_off,  wofh, wofl, 256, 144);    // 6
    k_wprep<<<(256*72  + 255) / 256, 256>>>(w_mask, wmkh, wmkl, 256, 72);     // 7
    k_wprep<<<(256*256 + 255) / 256, 256>>>(w_out,  wouh, woul, 256, 256);    // 8
    // depthwise + LN + GELU -> t (bf16 split)
    k_dw<<<NPIX, 256>>>(dw_w, dw_b, ln_g, ln_b);
    // offset & mask projections
    k_mma<<<dim3(128, 2), 256, SM_TOT>>>(th, tl, wofh, wofl, b_off,  off, 144, 256, 0, 0, 0, 0);
    k_mma<<<dim3(128, 1), 256, SM_TOT>>>(th, tl, wmkh, wmkl, b_mask, msk,  72, 256, 0, 0, 0, 0);
    // deformable sampling -> y (bf16 split)
    k_sample<<<NPIX, 256>>>();
    // output projection -> y2 (fp32)
    k_mma<<<dim3(128, 2), 256, SM_TOT>>>(yh, yl, wouh, woul, b_out, y2, 256, 256, 0, 0, 0, 0);
    // GN1 + SiLU -> bf16 split
    k_gn<<<128, 256>>>(y2, (float*)nullptr, gh, gl, gn1_g, gn1_b, 4096, 1, 0, 64);
    // conv1 3x3 implicit im2col (K=2304) -> y2
    k_mma<<<dim3(128, 2), 256, SM_TOT>>>(gh, gl, c1h, c1l, c1_b, y2, 256, 2304, 1, 6, 1, 0);
    // GN2 + SiLU -> bf16 split
    k_gn<<<128, 256>>>(y2, (float*)nullptr, gh, gl, gn2_g, gn2_b, 4096, 1, 0, 64);
    // down conv 3x3 stride2 (M=4096) -> dn
    k_mma<<<dim3(32, 2), 256, SM_TOT>>>(gh, gl, dwh, dwl, dn_b, dn, 256, 2304, 1, 5, 2, 0);
    // GN3 -> NCHW output
    k_gn<<<128, 256>>>(dn, (float*)d_out, (__nv_bfloat16*)nullptr, (__nv_bfloat16*)nullptr,
                       gn3_g, gn3_b, 1024, 0, 1, 32);
}

// round 5
// speedup vs baseline: 2.2434x; 1.1114x over previous
#include <cuda_runtime.h>
#include <cuda_fp16.h>
#include <cstdint>
#include <math.h>

#define NB   4
#define CC   256
#define HP   66
#define LPIX 4096
#define NPIX 16384

// ======================= PTX helpers ========================================
__device__ __forceinline__ uint32_t smem_u32(const void* p) {
    uint32_t a;
    asm("{ .reg .u64 t; cvta.to.shared.u64 t, %1; cvt.u32.u64 %0, t; }" : "=r"(a) : "l"(p));
    return a;
}
#define CP_ASYNC16(dst, src, sz) \
    asm volatile("cp.async.cg.shared.global [%0], [%1], 16, %2;" \
                 :: "r"(dst), "l"(src), "r"(sz) : "memory")
#define CP_COMMIT() asm volatile("cp.async.commit_group;" ::: "memory")
#define CP_WAIT(n)  asm volatile("cp.async.wait_group %0;" :: "n"(n) : "memory")

#define LDSM4(r0, r1, r2, r3, a) \
    asm volatile("ldmatrix.sync.aligned.m8n8.x4.shared.b16 {%0,%1,%2,%3}, [%4];" \
        : "=r"(r0), "=r"(r1), "=r"(r2), "=r"(r3) : "r"(a))

#define MMA_F16(acc, A, B) \
    asm volatile("mma.sync.aligned.m16n8k16.row.col.f32.f16.f16.f32 " \
        "{%0,%1,%2,%3}, {%4,%5,%6,%7}, {%8,%9}, {%0,%1,%2,%3};" \
        : "+f"((acc)[0]), "+f"((acc)[1]), "+f"((acc)[2]), "+f"((acc)[3]) \
        : "r"((A)[0]), "r"((A)[1]), "r"((A)[2]), "r"((A)[3]), \
          "r"((B)[0]), "r"((B)[1]))

__device__ __forceinline__ void hsplit(float v, __half& h, __half& l) {
    h = __float2half(v);
    l = __float2half(v - __half2float(h));
}

// ======================= scratch ============================================
__device__ float  g_xs [NPIX * CC];
__device__ __half g_xsh[NPIX * CC], g_xsl[NPIX * CC];
__device__ float  g_xp [NB * HP * HP * CC];
__device__ __half g_th [NPIX * CC], g_tl [NPIX * CC];
__device__ float  g_om [NPIX * 216];
__device__ float  g_bom[216];
__device__ __half g_yh [NPIX * CC], g_yl [NPIX * CC];
__device__ float  g_y2 [NPIX * CC];
__device__ __half g_gh [NPIX * CC], g_gl [NPIX * CC];
__device__ float  g_dn [NB * 32 * 32 * CC];
// weights: [N, K] fp16 (lo only where 3-term is used)
__device__ __half g_winh[256*256],  g_winl[256*256];
__device__ __half g_omh [216*256],  g_oml [216*256];
__device__ __half g_wouh[256*256],  g_woul[256*256];
__device__ __half g_c1h [256*2304];
__device__ __half g_dnh [256*2304];

// ======================= misc kernels =======================================
__device__ __forceinline__ void block_reduce2(float &a, float &b, float* sh) {
    int lane = threadIdx.x & 31, wid = threadIdx.x >> 5;
#pragma unroll
    for (int o = 16; o; o >>= 1) {
        a += __shfl_down_sync(0xffffffffu, a, o);
        b += __shfl_down_sync(0xffffffffu, b, o);
    }
    if (lane == 0) { sh[wid] = a; sh[8 + wid] = b; }
    __syncthreads();
    if (wid == 0) {
        a = (lane < 8) ? sh[lane] : 0.f;
        b = (lane < 8) ? sh[8 + lane] : 0.f;
#pragma unroll
        for (int o = 4; o; o >>= 1) {
            a += __shfl_down_sync(0xffffffffu, a, o);
            b += __shfl_down_sync(0xffffffffu, b, o);
        }
        if (lane == 0) { sh[16] = a; sh[17] = b; }
    }
    __syncthreads();
    a = sh[16]; b = sh[17];
}

__global__ void k_transpose(const float* __restrict__ x) {
    __shared__ float tile[32][33];
    int n  = blockIdx.z;
    int c0 = blockIdx.x * 32;
    int p0 = blockIdx.y * 32;
    int tx = threadIdx.x, ty = threadIdx.y;
#pragma unroll
    for (int j = 0; j < 32; j += 8)
        tile[ty + j][tx] = x[(size_t)(n * CC + c0 + ty + j) * LPIX + p0 + tx];
    __syncthreads();
#pragma unroll
    for (int j = 0; j < 32; j += 8) {
        float v = tile[tx][ty + j];
        size_t o = (size_t)(n * LPIX + p0 + ty + j) * CC + c0 + tx;
        g_xs[o] = v;
        __half h, l; hsplit(v, h, l);
        g_xsh[o] = h; g_xsl[o] = l;
    }
}

__global__ void k_zero_xp() {
    int i = blockIdx.x * blockDim.x + threadIdx.x;
    const int total4 = (NB * HP * HP * CC) / 4;
    if (i < total4)
        reinterpret_cast<float4*>(g_xp)[i] = make_float4(0.f, 0.f, 0.f, 0.f);
}

// tiled transpose weight prep: w [K,N] fp32 -> Wh (+opt Wl) [N,K] fp16
__global__ void k_wprep(const float* __restrict__ w, __half* __restrict__ Wh,
                        __half* __restrict__ Wl, int K, int N) {
    __shared__ float tile[32][33];
    int k0 = blockIdx.x * 32, n0 = blockIdx.y * 32;
    int tx = threadIdx.x, ty = threadIdx.y;   // 32 x 8
#pragma unroll
    for (int j = 0; j < 32; j += 8) {
        int k = k0 + ty + j, n = n0 + tx;
        tile[ty + j][tx] = (k < K && n < N) ? w[(size_t)k * N + n] : 0.f;
    }
    __syncthreads();
#pragma unroll
    for (int j = 0; j < 32; j += 8) {
        int n = n0 + ty + j, k = k0 + tx;
        if (n < N && k < K) {
            float v = tile[tx][ty + j];
            __half h = __float2half(v);
            Wh[(size_t)n * K + k] = h;
            if (Wl) Wl[(size_t)n * K + k] = __float2half(v - __half2float(h));
        }
    }
}

__global__ void k_bias_cat(const float* __restrict__ b1, const float* __restrict__ b2) {
    int i = threadIdx.x;
    if (i < 144) g_bom[i] = b1[i];
    else if (i < 216) g_bom[i] = b2[i - 144];
}

__global__ void k_dw(const float* __restrict__ dww, const float* __restrict__ dwb,
                     const float* __restrict__ lng, const float* __restrict__ lnb)
{
    int pix = blockIdx.x;
    int c   = threadIdx.x;
    int n = pix >> 12, h = (pix >> 6) & 63, w = pix & 63;
    float acc = dwb[c];
#pragma unroll
    for (int kh = 0; kh < 3; kh++) {
        int y = h + kh - 1;
        if ((unsigned)y >= 64u) continue;
#pragma unroll
        for (int kw = 0; kw < 3; kw++) {
            int x = w + kw - 1;
            if ((unsigned)x >= 64u) continue;
            acc += g_xs[((size_t)((n * 64 + y) * 64 + x)) * 256 + c] *
                   dww[(kh * 3 + kw) * 256 + c];
        }
    }
    __shared__ float sh[32];
    float s = acc, ss = acc * acc;
    block_reduce2(s, ss, sh);
    float mean = s * (1.f / 256.f);
    float var  = ss * (1.f / 256.f) - mean * mean;
    float rstd = rsqrtf(var + 1e-5f);
    float v = (acc - mean) * rstd * lng[c] + lnb[c];
    v = 0.5f * v * (1.f + erff(v * 0.70710678118654752440f));
    __half hh, ll; hsplit(v, hh, ll);
    g_th[(size_t)pix * 256 + c] = hh;
    g_tl[(size_t)pix * 256 + c] = ll;
}

__global__ void k_sample()
{
    int pix  = blockIdx.x;
    int g    = threadIdx.x >> 5;
    int lane = threadIdx.x & 31;
    int n = pix >> 12, h = (pix >> 6) & 63, w = pix & 63;

    const float* ml = g_om + (size_t)pix * 216 + 144 + g * 9;
    float e[9], mx = -1e30f, s = 0.f;
#pragma unroll
    for (int p = 0; p < 9; p++) mx = fmaxf(mx, ml[p]);
#pragma unroll
    for (int p = 0; p < 9; p++) { e[p] = expf(ml[p] - mx); s += e[p]; }
    float inv = 1.f / s;

    const float* off = g_om + (size_t)pix * 216 + g * 18;
    const float* img = g_xp + (size_t)n * HP * HP * CC + g * 32 + lane;
    float acc = 0.f;
#pragma unroll
    for (int p = 0; p < 9; p++) {
        float px = (float)(w + p / 3) + off[2 * p];
        float py = (float)(h + p % 3) + off[2 * p + 1];
        float wgt = e[p] * inv;
        float x0f = floorf(px), y0f = floorf(py);
        int x0 = (int)x0f, y0 = (int)y0f;
        float fx = px - x0f, fy = py - y0f;
#pragma unroll
        for (int dy = 0; dy < 2; dy++) {
            int yy = y0 + dy;
            if ((unsigned)yy >= (unsigned)HP) continue;
            float wy = dy ? fy : 1.f - fy;
#pragma unroll
            for (int dx = 0; dx < 2; dx++) {
                int xx = x0 + dx;
                if ((unsigned)xx >= (unsigned)HP) continue;
                float wx = dx ? fx : 1.f - fx;
                acc += img[((size_t)yy * HP + xx) * CC] * (wx * wy * wgt);
            }
        }
    }
    __half hh, ll; hsplit(acc, hh, ll);
    g_yh[(size_t)pix * 256 + g * 32 + lane] = hh;
    g_yl[(size_t)pix * 256 + g * 32 + lane] = ll;
}

// GroupNorm(32) [+SiLU]; optional second input summed in; fp32/NCHW and/or fp16 split out
__global__ void k_gn(const float* __restrict__ in, const float* __restrict__ in2,
                     float* __restrict__ outf,
                     __half* __restrict__ oh, __half* __restrict__ ol,
                     const float* __restrict__ gamma, const float* __restrict__ beta,
                     int HWn, int do_silu, int out_nchw, int Wd)
{
    int n = blockIdx.x >> 5;
    int g = blockIdx.x & 31;
    int cnt = HWn * 8;
    const float* base  = in  + (size_t)n * HWn * 256 + g * 8;
    const float* base2 = in2 ? in2 + (size_t)n * HWn * 256 + g * 8 : nullptr;
    float s = 0.f, ss = 0.f;
    for (int i = threadIdx.x; i < cnt; i += 256) {
        size_t o = (size_t)(i >> 3) * 256 + (i & 7);
        float v = base[o];
        if (base2) v += base2[o];
        s += v; ss += v * v;
    }
    __shared__ float sh[32];
    block_reduce2(s, ss, sh);
    float mean = s / (float)cnt;
    float rstd = rsqrtf(ss / (float)cnt - mean * mean + 1e-5f);
    for (int i = threadIdx.x; i < cnt; i += 256) {
        int l = i >> 3, c = i & 7;
        size_t o = (size_t)l * 256 + c;
        float v = base[o];
        if (base2) v += base2[o];
        v = (v - mean) * rstd * gamma[g * 8 + c] + beta[g * 8 + c];
        if (do_silu) v = v * (1.f / (1.f + expf(-v)));
        if (outf) {
            if (out_nchw)
                outf[(((size_t)n * 256 + g * 8 + c) * Wd + (l / Wd)) * Wd + (l % Wd)] = v;
            else
                outf[((size_t)n * HWn + l) * 256 + g * 8 + c] = v;
        }
        if (oh) {
            __half hh, ll; hsplit(v, hh, ll);
            size_t oo = ((size_t)n * HWn + l) * 256 + g * 8 + c;
            oh[oo] = hh; ol[oo] = ll;
        }
    }
}

// ======================= mma.sync split-fp16 GEMM ============================
// C = A*B + bias. 3-term (Bl!=null): Ah*Bh + Ah*Bl + Al*Bh (err ~2^-22)
//                 2-term (Bl==null): Ah*Bh + Al*Bh = A*Bh  (err ~2^-12)
// BK=64, 3-stage cp.async pipeline, ldmatrix + XOR swizzle.
// gridDim.z: K-split; z>0 writes partials to Cout2 without bias.
#define MATB   16384
#define STAGE  65536
#define SM_TOT 196608

__global__ void __launch_bounds__(256, 1)
k_mma(const __half* __restrict__ Ah, const __half* __restrict__ Al,
      const __half* __restrict__ Bh, const __half* __restrict__ Bl,
      const float* __restrict__ bias, float* __restrict__ Cout, float* __restrict__ Cout2,
      int N, int Kloc, int Kfull, int mode, int owbits, int stride, int padout)
{
    extern __shared__ __align__(128) char smem[];
    const uint32_t sb = smem_u32(smem);
    const int tid = threadIdx.x;
    const int wid = tid >> 5, lane = tid & 31;
    const int g = lane >> 2, tg = lane & 3;
    const int warpM = wid & 1, warpN = wid >> 1;
    const int m0 = blockIdx.x * 128;
    const int n0 = blockIdx.y * 128;
    const int kb = blockIdx.z * Kloc;
    float* Cbase = (blockIdx.z == 0) ? Cout : Cout2;
    const float* bias_eff = (blockIdx.z == 0) ? bias : nullptr;
    const bool three = (Bl != nullptr);
    const int S = Kloc >> 6;

    float acc[4][4][4];
#pragma unroll
    for (int i = 0; i < 4; i++)
#pragma unroll
        for (int j = 0; j < 4; j++)
#pragma unroll
            for (int r = 0; r < 4; r++) acc[i][j][r] = 0.f;

    auto fill = [&](int s, int st) {
        int gk = kb + (s << 6);
        int tap = gk >> 8, ci0 = gk & 255;
        int kh = tap / 3, kw = tap - 3 * kh;
        uint32_t stbase = sb + st * STAGE;
#pragma unroll 4
        for (int q = 0; q < 16; q++) {
            int cid = q * 256 + tid;           // 0..4095
            int mat = cid >> 10;
            if (mat == 3 && !three) break;     // mats ordered: skip Bl in 2-term
            int idx = cid & 1023;
            int r = idx >> 3, c = idx & 7;
            uint32_t dst = stbase + mat * MATB + r * 128 + ((c ^ (r & 7)) << 4);
            const __half* src;
            int sz = 16;
            if (mat < 2) {
                const __half* Ag = mat ? Al : Ah;
                int m = m0 + r;
                if (mode == 0) {
                    src = Ag + (size_t)m * Kfull + gk + c * 8;
                } else {
                    int nn = m >> (2 * owbits);
                    int hw = m & ((1 << (2 * owbits)) - 1);
                    int ohh = hw >> owbits, oww = hw & ((1 << owbits) - 1);
                    int iy = ohh * stride + kh - 1, ix = oww * stride + kw - 1;
                    if ((unsigned)iy < 64u && (unsigned)ix < 64u)
                        src = Ag + ((size_t)((nn * 64 + iy) * 64 + ix)) * 256 + ci0 + c * 8;
                    else { src = Ag; sz = 0; }
                }
            } else {
                const __half* Bg = (mat == 3) ? Bl : Bh;
                int n = n0 + r;
                if (n < N) src = Bg + (size_t)n * Kfull + gk + c * 8;
                else { src = Bg; sz = 0; }
            }
            CP_ASYNC16(dst, src, sz);
        }
    };

    const int lx = lane & 7;
    const uint32_t laneA_row = (uint32_t)(warpM * 64 + lx + ((lane >> 3) & 1) * 8) * 128;
    const uint32_t laneB_row = (uint32_t)(warpN * 32 + lx + ((lane >> 4) & 1) * 8) * 128;
    const int cselA = (lane >> 4) & 1;
    const int cselB = (lane >> 3) & 1;

    auto compute = [&](int st) {
        uint32_t bAh = sb + st * STAGE;
        uint32_t bAl = bAh + MATB;
        uint32_t bBh = bAh + 2 * MATB;
        uint32_t bBl = bAh + 3 * MATB;
#pragma unroll
        for (int kk = 0; kk < 4; kk++) {
            uint32_t swzA = (uint32_t)(((kk * 2 + cselA) ^ lx) << 4);
            uint32_t swzB = (uint32_t)(((kk * 2 + cselB) ^ lx) << 4);
            uint32_t ah[4][4], al_[4][4], bh[4][2], bl_[4][2];
#pragma unroll
            for (int mi = 0; mi < 4; mi++) {
                LDSM4(ah[mi][0], ah[mi][1], ah[mi][2], ah[mi][3],
                      bAh + laneA_row + mi * 2048 + swzA);
                LDSM4(al_[mi][0], al_[mi][1], al_[mi][2], al_[mi][3],
                      bAl + laneA_row + mi * 2048 + swzA);
            }
#pragma unroll
            for (int np = 0; np < 2; np++) {
                LDSM4(bh[np*2][0], bh[np*2][1], bh[np*2+1][0], bh[np*2+1][1],
                      bBh + laneB_row + np * 2048 + swzB);
                if (three)
                    LDSM4(bl_[np*2][0], bl_[np*2][1], bl_[np*2+1][0], bl_[np*2+1][1],
                          bBl + laneB_row + np * 2048 + swzB);
            }
#pragma unroll
            for (int mi = 0; mi < 4; mi++)
#pragma unroll
                for (int ni = 0; ni < 4; ni++) {
                    MMA_F16(acc[mi][ni], ah[mi], bh[ni]);
                    MMA_F16(acc[mi][ni], al_[mi], bh[ni]);
                    if (three) MMA_F16(acc[mi][ni], ah[mi], bl_[ni]);
                }
        }
    };

    // 3-stage pipeline, one barrier per stage
    fill(0, 0); CP_COMMIT();
    fill(1, 1); CP_COMMIT();
    int st = 0;
    for (int s = 0; s < S; s++) {
        CP_WAIT(1);
        __syncthreads();
        int st2 = st + 2; if (st2 >= 3) st2 -= 3;
        if (s + 2 < S) fill(s + 2, st2);
        CP_COMMIT();
        compute(st);
        if (++st == 3) st = 0;
    }

    // ---- epilogue ----
#pragma unroll
    for (int mi = 0; mi < 4; mi++) {
        int mA = m0 + warpM * 64 + mi * 16 + g;
#pragma unroll
        for (int half = 0; half < 2; half++) {
            int m = mA + half * 8;
            float* orow;
            if (padout) {
                int n = m >> 12, h = (m >> 6) & 63, w = m & 63;
                orow = Cbase + ((size_t)(n * HP + h + 1) * HP + (w + 1)) * 256;
            } else {
                orow = Cbase + (size_t)m * N;
            }
#pragma unroll
            for (int ni = 0; ni < 4; ni++) {
                int nc = n0 + warpN * 32 + ni * 8 + tg * 2;
                float b0 = bias_eff ? bias_eff[nc < N ? nc : 0] : 0.f;
                float b1 = bias_eff ? bias_eff[nc + 1 < N ? nc + 1 : 0] : 0.f;
                if (nc < N)     orow[nc]     = acc[mi][ni][half * 2]     + b0;
                if (nc + 1 < N) orow[nc + 1] = acc[mi][ni][half * 2 + 1] + b1;
            }
        }
    }
}

// ======================= launch =============================================
extern "C" void kernel_launch(void* const* d_in, const int* in_sizes, int n_in,
                              void* d_out, int out_size)
{
    const float* x      = (const float*)d_in[0];
    const float* w_in   = (const float*)d_in[1];
    const float* b_in   = (const float*)d_in[2];
    const float* dw_w   = (const float*)d_in[3];
    const float* dw_b   = (const float*)d_in[4];
    const float* ln_g   = (const float*)d_in[5];
    const float* ln_b   = (const float*)d_in[6];
    const float* w_off  = (const float*)d_in[7];
    const float* b_off  = (const float*)d_in[8];
    const float* w_mask = (const float*)d_in[9];
    const float* b_mask = (const float*)d_in[10];
    const float* w_out  = (const float*)d_in[11];
    const float* b_out  = (const float*)d_in[12];
    const float* gn1_g  = (const float*)d_in[13];
    const float* gn1_b  = (const float*)d_in[14];
    const float* c1_w   = (const float*)d_in[15];
    const float* c1_b   = (const float*)d_in[16];
    const float* gn2_g  = (const float*)d_in[17];
    const float* gn2_b  = (const float*)d_in[18];
    const float* dn_w   = (const float*)d_in[19];
    const float* dn_b   = (const float*)d_in[20];
    const float* gn3_g  = (const float*)d_in[21];
    const float* gn3_b  = (const float*)d_in[22];

    cudaFuncSetAttribute(k_mma, cudaFuncAttributeMaxDynamicSharedMemorySize, SM_TOT);

    float *xp, *om, *bom, *y2, *dn;
    __half *xsh, *xsl, *th, *tl, *yh, *yl, *gh, *gl;
    __half *winh, *winl, *omh, *oml, *wouh, *woul, *c1h, *dnh;
    cudaGetSymbolAddress((void**)&xp,  g_xp);
    cudaGetSymbolAddress((void**)&om,  g_om);
    cudaGetSymbolAddress((void**)&bom, g_bom);
    cudaGetSymbolAddress((void**)&y2,  g_y2);
    cudaGetSymbolAddress((void**)&dn,  g_dn);
    cudaGetSymbolAddress((void**)&xsh, g_xsh); cudaGetSymbolAddress((void**)&xsl, g_xsl);
    cudaGetSymbolAddress((void**)&th,  g_th);  cudaGetSymbolAddress((void**)&tl,  g_tl);
    cudaGetSymbolAddress((void**)&yh,  g_yh);  cudaGetSymbolAddress((void**)&yl,  g_yl);
    cudaGetSymbolAddress((void**)&gh,  g_gh);  cudaGetSymbolAddress((void**)&gl,  g_gl);
    cudaGetSymbolAddress((void**)&winh, g_winh); cudaGetSymbolAddress((void**)&winl, g_winl);
    cudaGetSymbolAddress((void**)&omh,  g_omh);  cudaGetSymbolAddress((void**)&oml,  g_oml);
    cudaGetSymbolAddress((void**)&wouh, g_wouh); cudaGetSymbolAddress((void**)&woul, g_woul);
    cudaGetSymbolAddress((void**)&c1h,  g_c1h);  cudaGetSymbolAddress((void**)&dnh,  g_dnh);

    dim3 wblk(32, 8);
    // 0..3 positioned so ncu's captured launch (#3 in prior rounds) is the inproj GEMM
    k_transpose<<<dim3(8, 128, 4), wblk>>>(x);                                   // 0
    k_zero_xp<<<(NB * HP * HP * CC / 4 + 255) / 256, 256>>>();                   // 1
    k_wprep<<<dim3(8, 8), wblk>>>(w_in, winh, winl, 256, 256);                   // 2
    // 3: input projection -> padded xp (3-term)
    k_mma<<<dim3(128, 2, 1), 256, SM_TOT>>>(xsh, xsl, winh, winl, b_in, xp, nullptr,
                                            256, 256, 256, 0, 0, 0, 1);
    // remaining weight preps
    k_wprep<<<dim3(8, 5), wblk>>>(w_off,  omh,             oml,             256, 144);
    k_wprep<<<dim3(8, 3), wblk>>>(w_mask, omh + 144 * 256, oml + 144 * 256, 256, 72);
    k_bias_cat<<<1, 256>>>(b_off, b_mask);
    k_wprep<<<dim3(8, 8),  wblk>>>(w_out, wouh, woul, 256, 256);
    k_wprep<<<dim3(72, 8), wblk>>>(c1_w, c1h, (__half*)nullptr, 2304, 256);
    k_wprep<<<dim3(72, 8), wblk>>>(dn_w, dnh, (__half*)nullptr, 2304, 256);
    // depthwise + LN + GELU -> t (fp16 split)
    k_dw<<<NPIX, 256>>>(dw_w, dw_b, ln_g, ln_b);
    // fused offset+mask projection (N=216, 3-term)
    k_mma<<<dim3(128, 2, 1), 256, SM_TOT>>>(th, tl, omh, oml, bom, om, nullptr,
                                            216, 256, 256, 0, 0, 0, 0);
    // deformable sampling -> y (fp16 split)
    k_sample<<<NPIX, 256>>>();
    // output projection -> y2 (3-term)
    k_mma<<<dim3(128, 2, 1), 256, SM_TOT>>>(yh, yl, wouh, woul, b_out, y2, nullptr,
                                            256, 256, 256, 0, 0, 0, 0);
    // GN1 + SiLU -> fp16 split
    k_gn<<<128, 256>>>(y2, nullptr, (float*)nullptr, gh, gl, gn1_g, gn1_b, 4096, 1, 0, 64);
    // conv1 3x3 implicit im2col (K=2304, 2-term) -> y2
    k_mma<<<dim3(128, 2, 1), 256, SM_TOT>>>(gh, gl, c1h, nullptr, c1_b, y2, nullptr,
                                            256, 2304, 2304, 1, 6, 1, 0);
    // GN2 + SiLU -> fp16 split
    k_gn<<<128, 256>>>(y2, nullptr, (float*)nullptr, gh, gl, gn2_g, gn2_b, 4096, 1, 0, 64);
    // down conv 3x3 stride2 (2-term, K-split z=2: dn + partial in y2)
    k_mma<<<dim3(32, 2, 2), 256, SM_TOT>>>(gh, gl, dnh, nullptr, dn_b, dn, y2,
                                           256, 1152, 2304, 1, 5, 2, 0);
    // GN3 (sums dn + y2 partial) -> NCHW output
    k_gn<<<128, 256>>>(dn, y2, (float*)d_out, (__half*)nullptr, (__half*)nullptr,
                       gn3_g, gn3_b, 1024, 0, 1, 32);
}

// round 6
// speedup vs baseline: 2.4897x; 1.1098x over previous
#include <cuda_runtime.h>
#include <cuda_fp16.h>
#include <cstdint>
#include <math.h>

#define NB   4
#define CC   256
#define HP   66
#define LPIX 4096
#define NPIX 16384

// ======================= PTX helpers ========================================
__device__ __forceinline__ uint32_t smem_u32(const void* p) {
    uint32_t a;
    asm("{ .reg .u64 t; cvta.to.shared.u64 t, %1; cvt.u32.u64 %0, t; }" : "=r"(a) : "l"(p));
    return a;
}
#define CP_ASYNC16(dst, src, sz) \
    asm volatile("cp.async.cg.shared.global [%0], [%1], 16, %2;" \
                 :: "r"(dst), "l"(src), "r"(sz) : "memory")
#define CP_COMMIT() asm volatile("cp.async.commit_group;" ::: "memory")
#define CP_WAIT(n)  asm volatile("cp.async.wait_group %0;" :: "n"(n) : "memory")

#define LDSM4(r0, r1, r2, r3, a) \
    asm volatile("ldmatrix.sync.aligned.m8n8.x4.shared.b16 {%0,%1,%2,%3}, [%4];" \
        : "=r"(r0), "=r"(r1), "=r"(r2), "=r"(r3) : "r"(a))

#define MMA_F16(acc, A, B) \
    asm volatile("mma.sync.aligned.m16n8k16.row.col.f32.f16.f16.f32 " \
        "{%0,%1,%2,%3}, {%4,%5,%6,%7}, {%8,%9}, {%0,%1,%2,%3};" \
        : "+f"((acc)[0]), "+f"((acc)[1]), "+f"((acc)[2]), "+f"((acc)[3]) \
        : "r"((A)[0]), "r"((A)[1]), "r"((A)[2]), "r"((A)[3]), \
          "r"((B)[0]), "r"((B)[1]))

__device__ __forceinline__ void hsplit(float v, __half& h, __half& l) {
    h = __float2half(v);
    l = __float2half(v - __half2float(h));
}

// ======================= scratch ============================================
__device__ float  g_xs [NPIX * CC];
__device__ __half g_xsh[NPIX * CC], g_xsl[NPIX * CC];
__device__ float  g_xp [NB * HP * HP * CC];
__device__ __half g_th [NPIX * CC], g_tl [NPIX * CC];
__device__ float  g_om [NPIX * 216];
__device__ float  g_bom[216];
__device__ __half g_yh [NPIX * CC], g_yl [NPIX * CC];
__device__ float  g_y2 [NPIX * CC];
__device__ __half g_gh [NPIX * CC], g_gl [NPIX * CC];
__device__ float  g_dn [NB * 32 * 32 * CC];
// weights: [N, K] fp16 (lo only where 3-term is used)
__device__ __half g_winh[256*256],  g_winl[256*256];
__device__ __half g_omh [216*256],  g_oml [216*256];
__device__ __half g_wouh[256*256],  g_woul[256*256];
__device__ __half g_c1h [256*2304];
__device__ __half g_dnh [256*2304];

// ======================= misc kernels =======================================
__device__ __forceinline__ void block_reduce2(float &a, float &b, float* sh) {
    int lane = threadIdx.x & 31, wid = threadIdx.x >> 5;
#pragma unroll
    for (int o = 16; o; o >>= 1) {
        a += __shfl_down_sync(0xffffffffu, a, o);
        b += __shfl_down_sync(0xffffffffu, b, o);
    }
    if (lane == 0) { sh[wid] = a; sh[8 + wid] = b; }
    __syncthreads();
    if (wid == 0) {
        a = (lane < 8) ? sh[lane] : 0.f;
        b = (lane < 8) ? sh[8 + lane] : 0.f;
#pragma unroll
        for (int o = 4; o; o >>= 1) {
            a += __shfl_down_sync(0xffffffffu, a, o);
            b += __shfl_down_sync(0xffffffffu, b, o);
        }
        if (lane == 0) { sh[16] = a; sh[17] = b; }
    }
    __syncthreads();
    a = sh[16]; b = sh[17];
}

__global__ void k_transpose(const float* __restrict__ x) {
    __shared__ float tile[32][33];
    int n  = blockIdx.z;
    int c0 = blockIdx.x * 32;
    int p0 = blockIdx.y * 32;
    int tx = threadIdx.x, ty = threadIdx.y;
#pragma unroll
    for (int j = 0; j < 32; j += 8)
        tile[ty + j][tx] = x[(size_t)(n * CC + c0 + ty + j) * LPIX + p0 + tx];
    __syncthreads();
#pragma unroll
    for (int j = 0; j < 32; j += 8) {
        float v = tile[tx][ty + j];
        size_t o = (size_t)(n * LPIX + p0 + ty + j) * CC + c0 + tx;
        g_xs[o] = v;
        __half h, l; hsplit(v, h, l);
        g_xsh[o] = h; g_xsl[o] = l;
    }
}

__global__ void k_zero_xp() {
    int i = blockIdx.x * blockDim.x + threadIdx.x;
    const int total4 = (NB * HP * HP * CC) / 4;
    if (i < total4)
        reinterpret_cast<float4*>(g_xp)[i] = make_float4(0.f, 0.f, 0.f, 0.f);
}

// tiled transpose weight prep: w [K,N] fp32 -> Wh (+opt Wl) [N,K] fp16
__global__ void k_wprep(const float* __restrict__ w, __half* __restrict__ Wh,
                        __half* __restrict__ Wl, int K, int N) {
    __shared__ float tile[32][33];
    int k0 = blockIdx.x * 32, n0 = blockIdx.y * 32;
    int tx = threadIdx.x, ty = threadIdx.y;   // 32 x 8
#pragma unroll
    for (int j = 0; j < 32; j += 8) {
        int k = k0 + ty + j, n = n0 + tx;
        tile[ty + j][tx] = (k < K && n < N) ? w[(size_t)k * N + n] : 0.f;
    }
    __syncthreads();
#pragma unroll
    for (int j = 0; j < 32; j += 8) {
        int n = n0 + ty + j, k = k0 + tx;
        if (n < N && k < K) {
            float v = tile[tx][ty + j];
            __half h = __float2half(v);
            Wh[(size_t)n * K + k] = h;
            if (Wl) Wl[(size_t)n * K + k] = __float2half(v - __half2float(h));
        }
    }
}

__global__ void k_bias_cat(const float* __restrict__ b1, const float* __restrict__ b2) {
    int i = threadIdx.x;
    if (i < 144) g_bom[i] = b1[i];
    else if (i < 216) g_bom[i] = b2[i - 144];
}

__global__ void k_dw(const float* __restrict__ dww, const float* __restrict__ dwb,
                     const float* __restrict__ lng, const float* __restrict__ lnb)
{
    int pix = blockIdx.x;
    int c   = threadIdx.x;
    int n = pix >> 12, h = (pix >> 6) & 63, w = pix & 63;
    float acc = dwb[c];
#pragma unroll
    for (int kh = 0; kh < 3; kh++) {
        int y = h + kh - 1;
        if ((unsigned)y >= 64u) continue;
#pragma unroll
        for (int kw = 0; kw < 3; kw++) {
            int x = w + kw - 1;
            if ((unsigned)x >= 64u) continue;
            acc += g_xs[((size_t)((n * 64 + y) * 64 + x)) * 256 + c] *
                   dww[(kh * 3 + kw) * 256 + c];
        }
    }
    __shared__ float sh[32];
    float s = acc, ss = acc * acc;
    block_reduce2(s, ss, sh);
    float mean = s * (1.f / 256.f);
    float var  = ss * (1.f / 256.f) - mean * mean;
    float rstd = rsqrtf(var + 1e-5f);
    float v = (acc - mean) * rstd * lng[c] + lnb[c];
    v = 0.5f * v * (1.f + erff(v * 0.70710678118654752440f));
    __half hh, ll; hsplit(v, hh, ll);
    g_th[(size_t)pix * 256 + c] = hh;
    g_tl[(size_t)pix * 256 + c] = ll;
}

__global__ void k_sample()
{
    int pix  = blockIdx.x;
    int g    = threadIdx.x >> 5;
    int lane = threadIdx.x & 31;
    int n = pix >> 12, h = (pix >> 6) & 63, w = pix & 63;

    const float* ml = g_om + (size_t)pix * 216 + 144 + g * 9;
    float e[9], mx = -1e30f, s = 0.f;
#pragma unroll
    for (int p = 0; p < 9; p++) mx = fmaxf(mx, ml[p]);
#pragma unroll
    for (int p = 0; p < 9; p++) { e[p] = expf(ml[p] - mx); s += e[p]; }
    float inv = 1.f / s;

    const float* off = g_om + (size_t)pix * 216 + g * 18;
    const float* img = g_xp + (size_t)n * HP * HP * CC + g * 32 + lane;
    float acc = 0.f;
#pragma unroll
    for (int p = 0; p < 9; p++) {
        float px = (float)(w + p / 3) + off[2 * p];
        float py = (float)(h + p % 3) + off[2 * p + 1];
        float wgt = e[p] * inv;
        float x0f = floorf(px), y0f = floorf(py);
        int x0 = (int)x0f, y0 = (int)y0f;
        float fx = px - x0f, fy = py - y0f;
#pragma unroll
        for (int dy = 0; dy < 2; dy++) {
            int yy = y0 + dy;
            if ((unsigned)yy >= (unsigned)HP) continue;
            float wy = dy ? fy : 1.f - fy;
#pragma unroll
            for (int dx = 0; dx < 2; dx++) {
                int xx = x0 + dx;
                if ((unsigned)xx >= (unsigned)HP) continue;
                float wx = dx ? fx : 1.f - fx;
                acc += img[((size_t)yy * HP + xx) * CC] * (wx * wy * wgt);
            }
        }
    }
    __half hh, ll; hsplit(acc, hh, ll);
    g_yh[(size_t)pix * 256 + g * 32 + lane] = hh;
    g_yl[(size_t)pix * 256 + g * 32 + lane] = ll;
}

// GroupNorm(32) [+SiLU]; optional second input summed in; fp32/NCHW and/or fp16 split out
__global__ void k_gn(const float* __restrict__ in, const float* __restrict__ in2,
                     float* __restrict__ outf,
                     __half* __restrict__ oh, __half* __restrict__ ol,
                     const float* __restrict__ gamma, const float* __restrict__ beta,
                     int HWn, int do_silu, int out_nchw, int Wd)
{
    int n = blockIdx.x >> 5;
    int g = blockIdx.x & 31;
    int cnt = HWn * 8;
    const float* base  = in  + (size_t)n * HWn * 256 + g * 8;
    const float* base2 = in2 ? in2 + (size_t)n * HWn * 256 + g * 8 : nullptr;
    float s = 0.f, ss = 0.f;
    for (int i = threadIdx.x; i < cnt; i += 256) {
        size_t o = (size_t)(i >> 3) * 256 + (i & 7);
        float v = base[o];
        if (base2) v += base2[o];
        s += v; ss += v * v;
    }
    __shared__ float sh[32];
    block_reduce2(s, ss, sh);
    float mean = s / (float)cnt;
    float rstd = rsqrtf(ss / (float)cnt - mean * mean + 1e-5f);
    for (int i = threadIdx.x; i < cnt; i += 256) {
        int l = i >> 3, c = i & 7;
        size_t o = (size_t)l * 256 + c;
        float v = base[o];
        if (base2) v += base2[o];
        v = (v - mean) * rstd * gamma[g * 8 + c] + beta[g * 8 + c];
        if (do_silu) v = v * (1.f / (1.f + expf(-v)));
        if (outf) {
            if (out_nchw)
                outf[(((size_t)n * 256 + g * 8 + c) * Wd + (l / Wd)) * Wd + (l % Wd)] = v;
            else
                outf[((size_t)n * HWn + l) * 256 + g * 8 + c] = v;
        }
        if (oh) {
            __half hh, ll; hsplit(v, hh, ll);
            size_t oo = ((size_t)n * HWn + l) * 256 + g * 8 + c;
            oh[oo] = hh; ol[oo] = ll;
        }
    }
}

// ======================= mma.sync split-fp16 GEMM ============================
// 512 threads, 16 warps (4M x 4N), warp tile 32x32, CTA tile 128x128, BK=64.
// 3-term (Bl!=null): Ah*Bh + Ah*Bl + Al*Bh ; 2-term: (Ah+Al)*Bh
#define MATB   16384
#define STAGE  65536
#define SM_T3  196608     // 3 stages x 4 mats
#define SM_T2  147456     // 3 stages x 3 mats (stride kept at STAGE? no — compact)

__global__ void __launch_bounds__(512, 1)
k_mma(const __half* __restrict__ Ah, const __half* __restrict__ Al,
      const __half* __restrict__ Bh, const __half* __restrict__ Bl,
      const float* __restrict__ bias, float* __restrict__ Cout, float* __restrict__ Cout2,
      int N, int Kloc, int Kfull, int mode, int owbits, int stride, int padout)
{
    extern __shared__ __align__(128) char smem[];
    const uint32_t sb = smem_u32(smem);
    const int tid = threadIdx.x;
    const int wid = tid >> 5, lane = tid & 31;
    const int g = lane >> 2, tg = lane & 3;
    const int warpM = wid & 3, warpN = wid >> 2;
    const int m0 = blockIdx.x * 128;
    const int n0 = blockIdx.y * 128;
    const int kb = blockIdx.z * Kloc;
    float* Cbase = (blockIdx.z == 0) ? Cout : Cout2;
    const float* bias_eff = (blockIdx.z == 0) ? bias : nullptr;
    const bool three = (Bl != nullptr);
    const int nmats = three ? 4 : 3;
    const uint32_t stagesz = (uint32_t)nmats * MATB;
    const int S = Kloc >> 6;

    float acc[2][4][4];
#pragma unroll
    for (int i = 0; i < 2; i++)
#pragma unroll
        for (int j = 0; j < 4; j++)
#pragma unroll
            for (int r = 0; r < 4; r++) acc[i][j][r] = 0.f;

    // mat order: 0=Ah, 1=Al, 2=Bh, 3=Bl(optional)
    auto fill = [&](int s, int st) {
        int gk = kb + (s << 6);
        int tap = gk >> 8, ci0 = gk & 255;
        int kh = tap / 3, kw = tap - 3 * kh;
        uint32_t stbase = sb + st * stagesz;
#pragma unroll 4
        for (int q = 0; q < 8; q++) {
            int cid = q * 512 + tid;           // 0..4095
            int mat = cid >> 10;
            if (mat >= nmats) break;
            int idx = cid & 1023;
            int r = idx >> 3, c = idx & 7;
            uint32_t dst = stbase + mat * MATB + r * 128 + ((c ^ (r & 7)) << 4);
            const __half* src;
            int sz = 16;
            if (mat < 2) {
                const __half* Ag = mat ? Al : Ah;
                int m = m0 + r;
                if (mode == 0) {
                    src = Ag + (size_t)m * Kfull + gk + c * 8;
                } else {
                    int nn = m >> (2 * owbits);
                    int hw = m & ((1 << (2 * owbits)) - 1);
                    int ohh = hw >> owbits, oww = hw & ((1 << owbits) - 1);
                    int iy = ohh * stride + kh - 1, ix = oww * stride + kw - 1;
                    if ((unsigned)iy < 64u && (unsigned)ix < 64u)
                        src = Ag + ((size_t)((nn * 64 + iy) * 64 + ix)) * 256 + ci0 + c * 8;
                    else { src = Ag; sz = 0; }
                }
            } else {
                const __half* Bg = (mat == 3) ? Bl : Bh;
                int n = n0 + r;
                if (n < N) src = Bg + (size_t)n * Kfull + gk + c * 8;
                else { src = Bg; sz = 0; }
            }
            CP_ASYNC16(dst, src, sz);
        }
    };

    const int lx = lane & 7;
    const uint32_t laneA_row = (uint32_t)(warpM * 32 + lx + ((lane >> 3) & 1) * 8) * 128;
    const uint32_t laneB_row = (uint32_t)(warpN * 32 + lx + ((lane >> 4) & 1) * 8) * 128;
    const int cselA = (lane >> 4) & 1;
    const int cselB = (lane >> 3) & 1;

    auto compute = [&](int st) {
        uint32_t bAh = sb + st * stagesz;
        uint32_t bAl = bAh + MATB;
        uint32_t bBh = bAh + 2 * MATB;
        uint32_t bBl = bAh + 3 * MATB;
#pragma unroll
        for (int kk = 0; kk < 4; kk++) {
            uint32_t swzA = (uint32_t)(((kk * 2 + cselA) ^ lx) << 4);
            uint32_t swzB = (uint32_t)(((kk * 2 + cselB) ^ lx) << 4);
            uint32_t ah[2][4], al_[2][4], bh[4][2], bl_[4][2];
#pragma unroll
            for (int mi = 0; mi < 2; mi++) {
                LDSM4(ah[mi][0], ah[mi][1], ah[mi][2], ah[mi][3],
                      bAh + laneA_row + mi * 2048 + swzA);
                LDSM4(al_[mi][0], al_[mi][1], al_[mi][2], al_[mi][3],
                      bAl + laneA_row + mi * 2048 + swzA);
            }
#pragma unroll
            for (int np = 0; np < 2; np++) {
                LDSM4(bh[np*2][0], bh[np*2][1], bh[np*2+1][0], bh[np*2+1][1],
                      bBh + laneB_row + np * 2048 + swzB);
                if (three)
                    LDSM4(bl_[np*2][0], bl_[np*2][1], bl_[np*2+1][0], bl_[np*2+1][1],
                          bBl + laneB_row + np * 2048 + swzB);
            }
#pragma unroll
            for (int mi = 0; mi < 2; mi++)
#pragma unroll
                for (int ni = 0; ni < 4; ni++) {
                    MMA_F16(acc[mi][ni], ah[mi], bh[ni]);
                    MMA_F16(acc[mi][ni], al_[mi], bh[ni]);
                    if (three) MMA_F16(acc[mi][ni], ah[mi], bl_[ni]);
                }
        }
    };

    // 3-stage pipeline, one barrier per stage
    fill(0, 0); CP_COMMIT();
    fill(1, 1); CP_COMMIT();
    int st = 0;
    for (int s = 0; s < S; s++) {
        CP_WAIT(1);
        __syncthreads();
        int st2 = st + 2; if (st2 >= 3) st2 -= 3;
        if (s + 2 < S) fill(s + 2, st2);
        CP_COMMIT();
        compute(st);
        if (++st == 3) st = 0;
    }

    // ---- epilogue ----
#pragma unroll
    for (int mi = 0; mi < 2; mi++) {
        int mA = m0 + warpM * 32 + mi * 16 + g;
#pragma unroll
        for (int half = 0; half < 2; half++) {
            int m = mA + half * 8;
            float* orow;
            if (padout) {
                int n = m >> 12, h = (m >> 6) & 63, w = m & 63;
                orow = Cbase + ((size_t)(n * HP + h + 1) * HP + (w + 1)) * 256;
            } else {
                orow = Cbase + (size_t)m * N;
            }
#pragma unroll
            for (int ni = 0; ni < 4; ni++) {
                int nc = n0 + warpN * 32 + ni * 8 + tg * 2;
                float b0 = bias_eff ? bias_eff[nc < N ? nc : 0] : 0.f;
                float b1 = bias_eff ? bias_eff[nc + 1 < N ? nc + 1 : 0] : 0.f;
                if (nc < N)     orow[nc]     = acc[mi][ni][half * 2]     + b0;
                if (nc + 1 < N) orow[nc + 1] = acc[mi][ni][half * 2 + 1] + b1;
            }
        }
    }
}

// ======================= launch =============================================
extern "C" void kernel_launch(void* const* d_in, const int* in_sizes, int n_in,
                              void* d_out, int out_size)
{
    const float* x      = (const float*)d_in[0];
    const float* w_in   = (const float*)d_in[1];
    const float* b_in   = (const float*)d_in[2];
    const float* dw_w   = (const float*)d_in[3];
    const float* dw_b   = (const float*)d_in[4];
    const float* ln_g   = (const float*)d_in[5];
    const float* ln_b   = (const float*)d_in[6];
    const float* w_off  = (const float*)d_in[7];
    const float* b_off  = (const float*)d_in[8];
    const float* w_mask = (const float*)d_in[9];
    const float* b_mask = (const float*)d_in[10];
    const float* w_out  = (const float*)d_in[11];
    const float* b_out  = (const float*)d_in[12];
    const float* gn1_g  = (const float*)d_in[13];
    const float* gn1_b  = (const float*)d_in[14];
    const float* c1_w   = (const float*)d_in[15];
    const float* c1_b   = (const float*)d_in[16];
    const float* gn2_g  = (const float*)d_in[17];
    const float* gn2_b  = (const float*)d_in[18];
    const float* dn_w   = (const float*)d_in[19];
    const float* dn_b   = (const float*)d_in[20];
    const float* gn3_g  = (const float*)d_in[21];
    const float* gn3_b  = (const float*)d_in[22];

    cudaFuncSetAttribute(k_mma, cudaFuncAttributeMaxDynamicSharedMemorySize, SM_T3);

    float *xp, *om, *bom, *y2, *dn;
    __half *xsh, *xsl, *th, *tl, *yh, *yl, *gh, *gl;
    __half *winh, *winl, *omh, *oml, *wouh, *woul, *c1h, *dnh;
    cudaGetSymbolAddress((void**)&xp,  g_xp);
    cudaGetSymbolAddress((void**)&om,  g_om);
    cudaGetSymbolAddress((void**)&bom, g_bom);
    cudaGetSymbolAddress((void**)&y2,  g_y2);
    cudaGetSymbolAddress((void**)&dn,  g_dn);
    cudaGetSymbolAddress((void**)&xsh, g_xsh); cudaGetSymbolAddress((void**)&xsl, g_xsl);
    cudaGetSymbolAddress((void**)&th,  g_th);  cudaGetSymbolAddress((void**)&tl,  g_tl);
    cudaGetSymbolAddress((void**)&yh,  g_yh);  cudaGetSymbolAddress((void**)&yl,  g_yl);
    cudaGetSymbolAddress((void**)&gh,  g_gh);  cudaGetSymbolAddress((void**)&gl,  g_gl);
    cudaGetSymbolAddress((void**)&winh, g_winh); cudaGetSymbolAddress((void**)&winl, g_winl);
    cudaGetSymbolAddress((void**)&omh,  g_omh);  cudaGetSymbolAddress((void**)&oml,  g_oml);
    cudaGetSymbolAddress((void**)&wouh, g_wouh); cudaGetSymbolAddress((void**)&woul, g_woul);
    cudaGetSymbolAddress((void**)&c1h,  g_c1h);  cudaGetSymbolAddress((void**)&dnh,  g_dnh);

    dim3 wblk(32, 8);
    k_transpose<<<dim3(8, 128, 4), wblk>>>(x);                                   // 0
    k_zero_xp<<<(NB * HP * HP * CC / 4 + 255) / 256, 256>>>();                   // 1
    k_wprep<<<dim3(8, 8), wblk>>>(w_in, winh, winl, 256, 256);                   // 2
    // 3: input projection -> padded xp (3-term)   [PROFILED LAUNCH]
    k_mma<<<dim3(128, 2, 1), 512, SM_T3>>>(xsh, xsl, winh, winl, b_in, xp, nullptr,
                                           256, 256, 256, 0, 0, 0, 1);
    // remaining weight preps
    k_wprep<<<dim3(8, 5), wblk>>>(w_off,  omh,             oml,             256, 144);
    k_wprep<<<dim3(8, 3), wblk>>>(w_mask, omh + 144 * 256, oml + 144 * 256, 256, 72);
    k_bias_cat<<<1, 256>>>(b_off, b_mask);
    k_wprep<<<dim3(8, 8),  wblk>>>(w_out, wouh, woul, 256, 256);
    k_wprep<<<dim3(72, 8), wblk>>>(c1_w, c1h, (__half*)nullptr, 2304, 256);
    k_wprep<<<dim3(72, 8), wblk>>>(dn_w, dnh, (__half*)nullptr, 2304, 256);
    // depthwise + LN + GELU -> t (fp16 split)
    k_dw<<<NPIX, 256>>>(dw_w, dw_b, ln_g, ln_b);
    // fused offset+mask projection (N=216, 3-term)
    k_mma<<<dim3(128, 2, 1), 512, SM_T3>>>(th, tl, omh, oml, bom, om, nullptr,
                                           216, 256, 256, 0, 0, 0, 0);
    // deformable sampling -> y (fp16 split)
    k_sample<<<NPIX, 256>>>();
    // output projection -> y2 (3-term)
    k_mma<<<dim3(128, 2, 1), 512, SM_T3>>>(yh, yl, wouh, woul, b_out, y2, nullptr,
                                           256, 256, 256, 0, 0, 0, 0);
    // GN1 + SiLU -> fp16 split
    k_gn<<<128, 256>>>(y2, nullptr, (float*)nullptr, gh, gl, gn1_g, gn1_b, 4096, 1, 0, 64);
    // conv1 3x3 implicit im2col (K=2304, 2-term) -> y2
    k_mma<<<dim3(128, 2, 1), 512, SM_T2>>>(gh, gl, c1h, nullptr, c1_b, y2, nullptr,
                                           256, 2304, 2304, 1, 6, 1, 0);
    // GN2 + SiLU -> fp16 split
    k_gn<<<128, 256>>>(y2, nullptr, (float*)nullptr, gh, gl, gn2_g, gn2_b, 4096, 1, 0, 64);
    // down conv 3x3 stride2 (2-term, K-split z=2: dn + partial in y2)
    k_mma<<<dim3(32, 2, 2), 512, SM_T2>>>(gh, gl, dnh, nullptr, dn_b, dn, y2,
                                          256, 1152, 2304, 1, 5, 2, 0);
    // GN3 (sums dn + y2 partial) -> NCHW output
    k_gn<<<128, 256>>>(dn, y2, (float*)d_out, (__half*)nullptr, (__half*)nullptr,
                       gn3_g, gn3_b, 1024, 0, 1, 32);
}

// round 7
// speedup vs baseline: 2.6268x; 1.0551x over previous
#include <cuda_runtime.h>
#include <cuda_fp16.h>
#include <cstdint>
#include <math.h>

#define NB   4
#define CC   256
#define HP   66
#define LPIX 4096
#define NPIX 16384

// ======================= PTX helpers ========================================
__device__ __forceinline__ uint32_t smem_u32(const void* p) {
    uint32_t a;
    asm("{ .reg .u64 t; cvta.to.shared.u64 t, %1; cvt.u32.u64 %0, t; }" : "=r"(a) : "l"(p));
    return a;
}
#define CP_ASYNC16(dst, src, sz) \
    asm volatile("cp.async.cg.shared.global [%0], [%1], 16, %2;" \
                 :: "r"(dst), "l"(src), "r"(sz) : "memory")
#define CP_COMMIT() asm volatile("cp.async.commit_group;" ::: "memory")
#define CP_WAIT(n)  asm volatile("cp.async.wait_group %0;" :: "n"(n) : "memory")

#define LDSM4(r0, r1, r2, r3, a) \
    asm volatile("ldmatrix.sync.aligned.m8n8.x4.shared.b16 {%0,%1,%2,%3}, [%4];" \
        : "=r"(r0), "=r"(r1), "=r"(r2), "=r"(r3) : "r"(a))

#define MMA_F16(acc, A, B) \
    asm volatile("mma.sync.aligned.m16n8k16.row.col.f32.f16.f16.f32 " \
        "{%0,%1,%2,%3}, {%4,%5,%6,%7}, {%8,%9}, {%0,%1,%2,%3};" \
        : "+f"((acc)[0]), "+f"((acc)[1]), "+f"((acc)[2]), "+f"((acc)[3]) \
        : "r"((A)[0]), "r"((A)[1]), "r"((A)[2]), "r"((A)[3]), \
          "r"((B)[0]), "r"((B)[1]))

__device__ __forceinline__ void hsplit(float v, __half& h, __half& l) {
    h = __float2half(v);
    l = __float2half(v - __half2float(h));
}

// ======================= scratch ============================================
__device__ float  g_xs [NPIX * CC];
__device__ __half g_xsh[NPIX * CC], g_xsl[NPIX * CC];
__device__ float  g_xp [NB * HP * HP * CC];
__device__ __half g_th [NPIX * CC], g_tl [NPIX * CC];
__device__ float  g_om [NPIX * 216];
__device__ float  g_bom[216];
__device__ __half g_yh [NPIX * CC], g_yl [NPIX * CC];
__device__ float  g_y2 [NPIX * CC];
__device__ __half g_gh [NPIX * CC], g_gl [NPIX * CC];
__device__ float  g_dn [NB * 32 * 32 * CC];
// weights: [N, K] fp16 (lo only where 3-term is used)
__device__ __half g_winh[256*256],  g_winl[256*256];
__device__ __half g_omh [216*256],  g_oml [216*256];
__device__ __half g_wouh[256*256],  g_woul[256*256];
__device__ __half g_c1h [256*2304];
__device__ __half g_dnh [256*2304];

// ======================= misc kernels =======================================
__device__ __forceinline__ void block_reduce2(float &a, float &b, float* sh) {
    int lane = threadIdx.x & 31, wid = threadIdx.x >> 5;
#pragma unroll
    for (int o = 16; o; o >>= 1) {
        a += __shfl_down_sync(0xffffffffu, a, o);
        b += __shfl_down_sync(0xffffffffu, b, o);
    }
    if (lane == 0) { sh[wid] = a; sh[8 + wid] = b; }
    __syncthreads();
    if (wid == 0) {
        a = (lane < 8) ? sh[lane] : 0.f;
        b = (lane < 8) ? sh[8 + lane] : 0.f;
#pragma unroll
        for (int o = 4; o; o >>= 1) {
            a += __shfl_down_sync(0xffffffffu, a, o);
            b += __shfl_down_sync(0xffffffffu, b, o);
        }
        if (lane == 0) { sh[16] = a; sh[17] = b; }
    }
    __syncthreads();
    a = sh[16]; b = sh[17];
}

__global__ void k_transpose(const float* __restrict__ x) {
    __shared__ float tile[32][33];
    int n  = blockIdx.z;
    int c0 = blockIdx.x * 32;
    int p0 = blockIdx.y * 32;
    int tx = threadIdx.x, ty = threadIdx.y;
#pragma unroll
    for (int j = 0; j < 32; j += 8)
        tile[ty + j][tx] = x[(size_t)(n * CC + c0 + ty + j) * LPIX + p0 + tx];
    __syncthreads();
#pragma unroll
    for (int j = 0; j < 32; j += 8) {
        float v = tile[tx][ty + j];
        size_t o = (size_t)(n * LPIX + p0 + ty + j) * CC + c0 + tx;
        g_xs[o] = v;
        __half h, l; hsplit(v, h, l);
        g_xsh[o] = h; g_xsl[o] = l;
    }
}

__global__ void k_zero_xp() {
    int i = blockIdx.x * blockDim.x + threadIdx.x;
    const int total4 = (NB * HP * HP * CC) / 4;
    if (i < total4)
        reinterpret_cast<float4*>(g_xp)[i] = make_float4(0.f, 0.f, 0.f, 0.f);
}

// tiled transpose weight prep: w [K,N] fp32 -> Wh (+opt Wl) [N,K] fp16
__global__ void k_wprep(const float* __restrict__ w, __half* __restrict__ Wh,
                        __half* __restrict__ Wl, int K, int N) {
    __shared__ float tile[32][33];
    int k0 = blockIdx.x * 32, n0 = blockIdx.y * 32;
    int tx = threadIdx.x, ty = threadIdx.y;   // 32 x 8
#pragma unroll
    for (int j = 0; j < 32; j += 8) {
        int k = k0 + ty + j, n = n0 + tx;
        tile[ty + j][tx] = (k < K && n < N) ? w[(size_t)k * N + n] : 0.f;
    }
    __syncthreads();
#pragma unroll
    for (int j = 0; j < 32; j += 8) {
        int n = n0 + ty + j, k = k0 + tx;
        if (n < N && k < K) {
            float v = tile[tx][ty + j];
            __half h = __float2half(v);
            Wh[(size_t)n * K + k] = h;
            if (Wl) Wl[(size_t)n * K + k] = __float2half(v - __half2float(h));
        }
    }
}

__global__ void k_bias_cat(const float* __restrict__ b1, const float* __restrict__ b2) {
    int i = threadIdx.x;
    if (i < 144) g_bom[i] = b1[i];
    else if (i < 216) g_bom[i] = b2[i - 144];
}

__global__ void k_dw(const float* __restrict__ dww, const float* __restrict__ dwb,
                     const float* __restrict__ lng, const float* __restrict__ lnb)
{
    int pix = blockIdx.x;
    int c   = threadIdx.x;
    int n = pix >> 12, h = (pix >> 6) & 63, w = pix & 63;
    float acc = dwb[c];
#pragma unroll
    for (int kh = 0; kh < 3; kh++) {
        int y = h + kh - 1;
        if ((unsigned)y >= 64u) continue;
#pragma unroll
        for (int kw = 0; kw < 3; kw++) {
            int x = w + kw - 1;
            if ((unsigned)x >= 64u) continue;
            acc += g_xs[((size_t)((n * 64 + y) * 64 + x)) * 256 + c] *
                   dww[(kh * 3 + kw) * 256 + c];
        }
    }
    __shared__ float sh[32];
    float s = acc, ss = acc * acc;
    block_reduce2(s, ss, sh);
    float mean = s * (1.f / 256.f);
    float var  = ss * (1.f / 256.f) - mean * mean;
    float rstd = rsqrtf(var + 1e-5f);
    float v = (acc - mean) * rstd * lng[c] + lnb[c];
    v = 0.5f * v * (1.f + erff(v * 0.70710678118654752440f));
    __half hh, ll; hsplit(v, hh, ll);
    g_th[(size_t)pix * 256 + c] = hh;
    g_tl[(size_t)pix * 256 + c] = ll;
}

__global__ void k_sample()
{
    int pix  = blockIdx.x;
    int g    = threadIdx.x >> 5;
    int lane = threadIdx.x & 31;
    int n = pix >> 12, h = (pix >> 6) & 63, w = pix & 63;

    const float* ml = g_om + (size_t)pix * 216 + 144 + g * 9;
    float e[9], mx = -1e30f, s = 0.f;
#pragma unroll
    for (int p = 0; p < 9; p++) mx = fmaxf(mx, ml[p]);
#pragma unroll
    for (int p = 0; p < 9; p++) { e[p] = expf(ml[p] - mx); s += e[p]; }
    float inv = 1.f / s;

    const float* off = g_om + (size_t)pix * 216 + g * 18;
    const float* img = g_xp + (size_t)n * HP * HP * CC + g * 32 + lane;
    float acc = 0.f;
#pragma unroll
    for (int p = 0; p < 9; p++) {
        float px = (float)(w + p / 3) + off[2 * p];
        float py = (float)(h + p % 3) + off[2 * p + 1];
        float wgt = e[p] * inv;
        float x0f = floorf(px), y0f = floorf(py);
        int x0 = (int)x0f, y0 = (int)y0f;
        float fx = px - x0f, fy = py - y0f;
#pragma unroll
        for (int dy = 0; dy < 2; dy++) {
            int yy = y0 + dy;
            if ((unsigned)yy >= (unsigned)HP) continue;
            float wy = dy ? fy : 1.f - fy;
#pragma unroll
            for (int dx = 0; dx < 2; dx++) {
                int xx = x0 + dx;
                if ((unsigned)xx >= (unsigned)HP) continue;
                float wx = dx ? fx : 1.f - fx;
                acc += img[((size_t)yy * HP + xx) * CC] * (wx * wy * wgt);
            }
        }
    }
    __half hh, ll; hsplit(acc, hh, ll);
    g_yh[(size_t)pix * 256 + g * 32 + lane] = hh;
    g_yl[(size_t)pix * 256 + g * 32 + lane] = ll;
}

// GroupNorm(32) [+SiLU]; optional second input summed in; fp32/NCHW and/or fp16 split out
__global__ void k_gn(const float* __restrict__ in, const float* __restrict__ in2,
                     float* __restrict__ outf,
                     __half* __restrict__ oh, __half* __restrict__ ol,
                     const float* __restrict__ gamma, const float* __restrict__ beta,
                     int HWn, int do_silu, int out_nchw, int Wd)
{
    int n = blockIdx.x >> 5;
    int g = blockIdx.x & 31;
    int cnt = HWn * 8;
    const float* base  = in  + (size_t)n * HWn * 256 + g * 8;
    const float* base2 = in2 ? in2 + (size_t)n * HWn * 256 + g * 8 : nullptr;
    float s = 0.f, ss = 0.f;
    for (int i = threadIdx.x; i < cnt; i += 256) {
        size_t o = (size_t)(i >> 3) * 256 + (i & 7);
        float v = base[o];
        if (base2) v += base2[o];
        s += v; ss += v * v;
    }
    __shared__ float sh[32];
    block_reduce2(s, ss, sh);
    float mean = s / (float)cnt;
    float rstd = rsqrtf(ss / (float)cnt - mean * mean + 1e-5f);
    for (int i = threadIdx.x; i < cnt; i += 256) {
        int l = i >> 3, c = i & 7;
        size_t o = (size_t)l * 256 + c;
        float v = base[o];
        if (base2) v += base2[o];
        v = (v - mean) * rstd * gamma[g * 8 + c] + beta[g * 8 + c];
        if (do_silu) v = v * (1.f / (1.f + expf(-v)));
        if (outf) {
            if (out_nchw)
                outf[(((size_t)n * 256 + g * 8 + c) * Wd + (l / Wd)) * Wd + (l % Wd)] = v;
            else
                outf[((size_t)n * HWn + l) * 256 + g * 8 + c] = v;
        }
        if (oh) {
            __half hh, ll; hsplit(v, hh, ll);
            size_t oo = ((size_t)n * HWn + l) * 256 + g * 8 + c;
            oh[oo] = hh; ol[oo] = ll;
        }
    }
}

// ======================= mma.sync split-fp16 GEMM ============================
// 512 threads, 16 warps (4M x 4N), warp tile 32x32, CTA tile 128x128, BK=64.
// 3-term (Bl!=null): Ah*Bh + Ah*Bl + Al*Bh, 3 stages, wait(1)
// 2-term (Bl==null): Ah*Bh + Al*Bh, 4 stages, wait(2)
// Term-major MMA ordering: 8 independent accumulators between RAW reuses.
#define MATB   16384
#define SM_TOT 196608

__global__ void __launch_bounds__(512, 1)
k_mma(const __half* __restrict__ Ah, const __half* __restrict__ Al,
      const __half* __restrict__ Bh, const __half* __restrict__ Bl,
      const float* __restrict__ bias, float* __restrict__ Cout, float* __restrict__ Cout2,
      int N, int Kloc, int Kfull, int mode, int owbits, int stride, int padout)
{
    extern __shared__ __align__(128) char smem[];
    const uint32_t sb = smem_u32(smem);
    const int tid = threadIdx.x;
    const int wid = tid >> 5, lane = tid & 31;
    const int g = lane >> 2, tg = lane & 3;
    const int warpM = wid & 3, warpN = wid >> 2;
    const int m0 = blockIdx.x * 128;
    const int n0 = blockIdx.y * 128;
    const int kb = blockIdx.z * Kloc;
    float* Cbase = (blockIdx.z == 0) ? Cout : Cout2;
    const float* bias_eff = (blockIdx.z == 0) ? bias : nullptr;
    const bool three = (Bl != nullptr);
    const int nmats  = three ? 4 : 3;
    const int depth  = three ? 3 : 4;
    const uint32_t stagesz = (uint32_t)nmats * MATB;
    const int S = Kloc >> 6;

    float acc[2][4][4];
#pragma unroll
    for (int i = 0; i < 2; i++)
#pragma unroll
        for (int j = 0; j < 4; j++)
#pragma unroll
            for (int r = 0; r < 4; r++) acc[i][j][r] = 0.f;

    // mat order: 0=Ah, 1=Al, 2=Bh, 3=Bl(optional)
    auto fill = [&](int s, int st) {
        int gk = kb + (s << 6);
        int tap = gk >> 8, ci0 = gk & 255;
        int kh = tap / 3, kw = tap - 3 * kh;
        uint32_t stbase = sb + st * stagesz;
#pragma unroll 4
        for (int q = 0; q < 8; q++) {
            int cid = q * 512 + tid;           // 0..4095
            int mat = cid >> 10;
            if (mat >= nmats) break;
            int idx = cid & 1023;
            int r = idx >> 3, c = idx & 7;
            uint32_t dst = stbase + mat * MATB + r * 128 + ((c ^ (r & 7)) << 4);
            const __half* src;
            int sz = 16;
            if (mat < 2) {
                const __half* Ag = mat ? Al : Ah;
                int m = m0 + r;
                if (mode == 0) {
                    src = Ag + (size_t)m * Kfull + gk + c * 8;
                } else {
                    int nn = m >> (2 * owbits);
                    int hw = m & ((1 << (2 * owbits)) - 1);
                    int ohh = hw >> owbits, oww = hw & ((1 << owbits) - 1);
                    int iy = ohh * stride + kh - 1, ix = oww * stride + kw - 1;
                    if ((unsigned)iy < 64u && (unsigned)ix < 64u)
                        src = Ag + ((size_t)((nn * 64 + iy) * 64 + ix)) * 256 + ci0 + c * 8;
                    else { src = Ag; sz = 0; }
                }
            } else {
                const __half* Bg = (mat == 3) ? Bl : Bh;
                int n = n0 + r;
                if (n < N) src = Bg + (size_t)n * Kfull + gk + c * 8;
                else { src = Bg; sz = 0; }
            }
            CP_ASYNC16(dst, src, sz);
        }
    };

    const int lx = lane & 7;
    const uint32_t laneA_row = (uint32_t)(warpM * 32 + lx + ((lane >> 3) & 1) * 8) * 128;
    const uint32_t laneB_row = (uint32_t)(warpN * 32 + lx + ((lane >> 4) & 1) * 8) * 128;
    const int cselA = (lane >> 4) & 1;
    const int cselB = (lane >> 3) & 1;

    auto compute = [&](int st) {
        uint32_t bAh = sb + st * stagesz;
        uint32_t bAl = bAh + MATB;
        uint32_t bBh = bAh + 2 * MATB;
        uint32_t bBl = bAh + 3 * MATB;
#pragma unroll
        for (int kk = 0; kk < 4; kk++) {
            uint32_t swzA = (uint32_t)(((kk * 2 + cselA) ^ lx) << 4);
            uint32_t swzB = (uint32_t)(((kk * 2 + cselB) ^ lx) << 4);
            uint32_t ah[2][4], al_[2][4], bh[4][2], bl_[4][2];
#pragma unroll
            for (int mi = 0; mi < 2; mi++) {
                LDSM4(ah[mi][0], ah[mi][1], ah[mi][2], ah[mi][3],
                      bAh + laneA_row + mi * 2048 + swzA);
                LDSM4(al_[mi][0], al_[mi][1], al_[mi][2], al_[mi][3],
                      bAl + laneA_row + mi * 2048 + swzA);
            }
#pragma unroll
            for (int np = 0; np < 2; np++) {
                LDSM4(bh[np*2][0], bh[np*2][1], bh[np*2+1][0], bh[np*2+1][1],
                      bBh + laneB_row + np * 2048 + swzB);
                if (three)
                    LDSM4(bl_[np*2][0], bl_[np*2][1], bl_[np*2+1][0], bl_[np*2+1][1],
                          bBl + laneB_row + np * 2048 + swzB);
            }
            // term-major: 8 independent accs between same-acc reuses
#pragma unroll
            for (int mi = 0; mi < 2; mi++)
#pragma unroll
                for (int ni = 0; ni < 4; ni++)
                    MMA_F16(acc[mi][ni], ah[mi], bh[ni]);
#pragma unroll
            for (int mi = 0; mi < 2; mi++)
#pragma unroll
                for (int ni = 0; ni < 4; ni++)
                    MMA_F16(acc[mi][ni], al_[mi], bh[ni]);
            if (three) {
#pragma unroll
                for (int mi = 0; mi < 2; mi++)
#pragma unroll
                    for (int ni = 0; ni < 4; ni++)
                        MMA_F16(acc[mi][ni], ah[mi], bl_[ni]);
            }
        }
    };

    // multistage pipeline, one barrier per stage
    for (int s = 0; s < depth - 1; s++) { fill(s, s); CP_COMMIT(); }
    int st = 0;
    for (int s = 0; s < S; s++) {
        if (three) CP_WAIT(1); else CP_WAIT(2);
        __syncthreads();
        int stf = st + depth - 1; if (stf >= depth) stf -= depth;
        if (s + depth - 1 < S) fill(s + depth - 1, stf);
        CP_COMMIT();
        compute(st);
        if (++st == depth) st = 0;
    }

    // ---- epilogue ----
#pragma unroll
    for (int mi = 0; mi < 2; mi++) {
        int mA = m0 + warpM * 32 + mi * 16 + g;
#pragma unroll
        for (int half = 0; half < 2; half++) {
            int m = mA + half * 8;
            float* orow;
            if (padout) {
                int n = m >> 12, h = (m >> 6) & 63, w = m & 63;
                orow = Cbase + ((size_t)(n * HP + h + 1) * HP + (w + 1)) * 256;
            } else {
                orow = Cbase + (size_t)m * N;
            }
#pragma unroll
            for (int ni = 0; ni < 4; ni++) {
                int nc = n0 + warpN * 32 + ni * 8 + tg * 2;
                float b0 = bias_eff ? bias_eff[nc < N ? nc : 0] : 0.f;
                float b1 = bias_eff ? bias_eff[nc + 1 < N ? nc + 1 : 0] : 0.f;
                if (nc < N)     orow[nc]     = acc[mi][ni][half * 2]     + b0;
                if (nc + 1 < N) orow[nc + 1] = acc[mi][ni][half * 2 + 1] + b1;
            }
        }
    }
}

// ======================= launch =============================================
extern "C" void kernel_launch(void* const* d_in, const int* in_sizes, int n_in,
                              void* d_out, int out_size)
{
    const float* x      = (const float*)d_in[0];
    const float* w_in   = (const float*)d_in[1];
    const float* b_in   = (const float*)d_in[2];
    const float* dw_w   = (const float*)d_in[3];
    const float* dw_b   = (const float*)d_in[4];
    const float* ln_g   = (const float*)d_in[5];
    const float* ln_b   = (const float*)d_in[6];
    const float* w_off  = (const float*)d_in[7];
    const float* b_off  = (const float*)d_in[8];
    const float* w_mask = (const float*)d_in[9];
    const float* b_mask = (const float*)d_in[10];
    const float* w_out  = (const float*)d_in[11];
    const float* b_out  = (const float*)d_in[12];
    const float* gn1_g  = (const float*)d_in[13];
    const float* gn1_b  = (const float*)d_in[14];
    const float* c1_w   = (const float*)d_in[15];
    const float* c1_b   = (const float*)d_in[16];
    const float* gn2_g  = (const float*)d_in[17];
    const float* gn2_b  = (const float*)d_in[18];
    const float* dn_w   = (const float*)d_in[19];
    const float* dn_b   = (const float*)d_in[20];
    const float* gn3_g  = (const float*)d_in[21];
    const float* gn3_b  = (const float*)d_in[22];

    cudaFuncSetAttribute(k_mma, cudaFuncAttributeMaxDynamicSharedMemorySize, SM_TOT);

    float *xp, *om, *bom, *y2, *dn;
    __half *xsh, *xsl, *th, *tl, *yh, *yl, *gh, *gl;
    __half *winh, *winl, *omh, *oml, *wouh, *woul, *c1h, *dnh;
    cudaGetSymbolAddress((void**)&xp,  g_xp);
    cudaGetSymbolAddress((void**)&om,  g_om);
    cudaGetSymbolAddress((void**)&bom, g_bom);
    cudaGetSymbolAddress((void**)&y2,  g_y2);
    cudaGetSymbolAddress((void**)&dn,  g_dn);
    cudaGetSymbolAddress((void**)&xsh, g_xsh); cudaGetSymbolAddress((void**)&xsl, g_xsl);
    cudaGetSymbolAddress((void**)&th,  g_th);  cudaGetSymbolAddress((void**)&tl,  g_tl);
    cudaGetSymbolAddress((void**)&yh,  g_yh);  cudaGetSymbolAddress((void**)&yl,  g_yl);
    cudaGetSymbolAddress((void**)&gh,  g_gh);  cudaGetSymbolAddress((void**)&gl,  g_gl);
    cudaGetSymbolAddress((void**)&winh, g_winh); cudaGetSymbolAddress((void**)&winl, g_winl);
    cudaGetSymbolAddress((void**)&omh,  g_omh);  cudaGetSymbolAddress((void**)&oml,  g_oml);
    cudaGetSymbolAddress((void**)&wouh, g_wouh); cudaGetSymbolAddress((void**)&woul, g_woul);
    cudaGetSymbolAddress((void**)&c1h,  g_c1h);  cudaGetSymbolAddress((void**)&dnh,  g_dnh);

    dim3 wblk(32, 8);
    k_transpose<<<dim3(8, 128, 4), wblk>>>(x);                                   // 0
    k_zero_xp<<<(NB * HP * HP * CC / 4 + 255) / 256, 256>>>();                   // 1
    k_wprep<<<dim3(8, 8), wblk>>>(w_in, winh, winl, 256, 256);                   // 2
    // 3: input projection -> padded xp (3-term)   [PROFILED LAUNCH]
    k_mma<<<dim3(128, 2, 1), 512, SM_TOT>>>(xsh, xsl, winh, winl, b_in, xp, nullptr,
                                            256, 256, 256, 0, 0, 0, 1);
    // remaining weight preps
    k_wprep<<<dim3(8, 5), wblk>>>(w_off,  omh,             oml,             256, 144);
    k_wprep<<<dim3(8, 3), wblk>>>(w_mask, omh + 144 * 256, oml + 144 * 256, 256, 72);
    k_bias_cat<<<1, 256>>>(b_off, b_mask);
    k_wprep<<<dim3(8, 8),  wblk>>>(w_out, wouh, woul, 256, 256);
    k_wprep<<<dim3(72, 8), wblk>>>(c1_w, c1h, (__half*)nullptr, 2304, 256);
    k_wprep<<<dim3(72, 8), wblk>>>(dn_w, dnh, (__half*)nullptr, 2304, 256);
    // depthwise + LN + GELU -> t (fp16 split)
    k_dw<<<NPIX, 256>>>(dw_w, dw_b, ln_g, ln_b);
    // fused offset+mask projection (N=216, 3-term)
    k_mma<<<dim3(128, 2, 1), 512, SM_TOT>>>(th, tl, omh, oml, bom, om, nullptr,
                                            216, 256, 256, 0, 0, 0, 0);
    // deformable sampling -> y (fp16 split)
    k_sample<<<NPIX, 256>>>();
    // output projection -> y2 (3-term)
    k_mma<<<dim3(128, 2, 1), 512, SM_TOT>>>(yh, yl, wouh, woul, b_out, y2, nullptr,
                                            256, 256, 256, 0, 0, 0, 0);
    // GN1 + SiLU -> fp16 split
    k_gn<<<128, 256>>>(y2, nullptr, (float*)nullptr, gh, gl, gn1_g, gn1_b, 4096, 1, 0, 64);
    // conv1 3x3 implicit im2col (K=2304, 2-term, 4-stage) -> y2
    k_mma<<<dim3(128, 2, 1), 512, SM_TOT>>>(gh, gl, c1h, nullptr, c1_b, y2, nullptr,
                                            256, 2304, 2304, 1, 6, 1, 0);
    // GN2 + SiLU -> fp16 split
    k_gn<<<128, 256>>>(y2, nullptr, (float*)nullptr, gh, gl, gn2_g, gn2_b, 4096, 1, 0, 64);
    // down conv 3x3 stride2 (2-term, K-split z=2: dn + partial in y2)
    k_mma<<<dim3(32, 2, 2), 512, SM_TOT>>>(gh, gl, dnh, nullptr, dn_b, dn, y2,
                                           256, 1152, 2304, 1, 5, 2, 0);
    // GN3 (sums dn + y2 partial) -> NCHW output
    k_gn<<<128, 256>>>(dn, y2, (float*)d_out, (__half*)nullptr, (__half*)nullptr,
                       gn3_g, gn3_b, 1024, 0, 1, 32);
}

// round 8
// speedup vs baseline: 3.0837x; 1.1739x over previous
#include <cuda_runtime.h>
#include <cuda_fp16.h>
#include <cstdint>
#include <math.h>

#define NB   4
#define CC   256
#define HP   66
#define LPIX 4096
#define NPIX 16384

// ======================= PTX helpers ========================================
__device__ __forceinline__ uint32_t smem_u32(const void* p) {
    uint32_t a;
    asm("{ .reg .u64 t; cvta.to.shared.u64 t, %1; cvt.u32.u64 %0, t; }" : "=r"(a) : "l"(p));
    return a;
}
#define CP_ASYNC16(dst, src, sz) \
    asm volatile("cp.async.cg.shared.global [%0], [%1], 16, %2;" \
                 :: "r"(dst), "l"(src), "r"(sz) : "memory")
#define CP_COMMIT() asm volatile("cp.async.commit_group;" ::: "memory")
#define CP_WAIT(n)  asm volatile("cp.async.wait_group %0;" :: "n"(n) : "memory")

#define LDSM4(r0, r1, r2, r3, a) \
    asm volatile("ldmatrix.sync.aligned.m8n8.x4.shared.b16 {%0,%1,%2,%3}, [%4];" \
        : "=r"(r0), "=r"(r1), "=r"(r2), "=r"(r3) : "r"(a))

#define MMA_F16(acc, A, B) \
    asm volatile("mma.sync.aligned.m16n8k16.row.col.f32.f16.f16.f32 " \
        "{%0,%1,%2,%3}, {%4,%5,%6,%7}, {%8,%9}, {%0,%1,%2,%3};" \
        : "+f"((acc)[0]), "+f"((acc)[1]), "+f"((acc)[2]), "+f"((acc)[3]) \
        : "r"((A)[0]), "r"((A)[1]), "r"((A)[2]), "r"((A)[3]), \
          "r"((B)[0]), "r"((B)[1]))

__device__ __forceinline__ void hsplit(float v, __half& h, __half& l) {
    h = __float2half(v);
    l = __float2half(v - __half2float(h));
}

// ======================= scratch ============================================
__device__ float  g_xs [NPIX * CC];
__device__ __half g_xsh[NPIX * CC], g_xsl[NPIX * CC];
__device__ float  g_xp [NB * HP * HP * CC];
__device__ __half g_th [NPIX * CC], g_tl [NPIX * CC];
__device__ float  g_om [NPIX * 216];
__device__ float  g_bom[216];
__device__ __half g_yh [NPIX * CC], g_yl [NPIX * CC];
__device__ float  g_y2 [NPIX * CC];
__device__ __half g_gh [NPIX * CC];
__device__ float  g_dn [NB * 32 * 32 * CC];
// weights: [N, K] fp16 (lo only where 3-term is used)
__device__ __half g_winh[256*256],  g_winl[256*256];
__device__ __half g_omh [216*256],  g_oml [216*256];
__device__ __half g_wouh[256*256],  g_woul[256*256];
__device__ __half g_c1h [256*2304];
__device__ __half g_dnh [256*2304];

// ======================= misc kernels =======================================
__device__ __forceinline__ void block_reduce2(float &a, float &b, float* sh) {
    int lane = threadIdx.x & 31, wid = threadIdx.x >> 5;
#pragma unroll
    for (int o = 16; o; o >>= 1) {
        a += __shfl_down_sync(0xffffffffu, a, o);
        b += __shfl_down_sync(0xffffffffu, b, o);
    }
    if (lane == 0) { sh[wid] = a; sh[8 + wid] = b; }
    __syncthreads();
    if (wid == 0) {
        a = (lane < 8) ? sh[lane] : 0.f;
        b = (lane < 8) ? sh[8 + lane] : 0.f;
#pragma unroll
        for (int o = 4; o; o >>= 1) {
            a += __shfl_down_sync(0xffffffffu, a, o);
            b += __shfl_down_sync(0xffffffffu, b, o);
        }
        if (lane == 0) { sh[16] = a; sh[17] = b; }
    }
    __syncthreads();
    a = sh[16]; b = sh[17];
}

__global__ void k_transpose(const float* __restrict__ x) {
    __shared__ float tile[32][33];
    int n  = blockIdx.z;
    int c0 = blockIdx.x * 32;
    int p0 = blockIdx.y * 32;
    int tx = threadIdx.x, ty = threadIdx.y;
#pragma unroll
    for (int j = 0; j < 32; j += 8)
        tile[ty + j][tx] = x[(size_t)(n * CC + c0 + ty + j) * LPIX + p0 + tx];
    __syncthreads();
#pragma unroll
    for (int j = 0; j < 32; j += 8) {
        float v = tile[tx][ty + j];
        size_t o = (size_t)(n * LPIX + p0 + ty + j) * CC + c0 + tx;
        g_xs[o] = v;
        __half h, l; hsplit(v, h, l);
        g_xsh[o] = h; g_xsl[o] = l;
    }
}

__global__ void k_zero_xp() {
    int i = blockIdx.x * blockDim.x + threadIdx.x;
    const int total4 = (NB * HP * HP * CC) / 4;
    if (i < total4)
        reinterpret_cast<float4*>(g_xp)[i] = make_float4(0.f, 0.f, 0.f, 0.f);
}

// tiled transpose weight prep: w [K,N] fp32 -> Wh (+opt Wl) [N,K] fp16
__global__ void k_wprep(const float* __restrict__ w, __half* __restrict__ Wh,
                        __half* __restrict__ Wl, int K, int N) {
    __shared__ float tile[32][33];
    int k0 = blockIdx.x * 32, n0 = blockIdx.y * 32;
    int tx = threadIdx.x, ty = threadIdx.y;   // 32 x 8
#pragma unroll
    for (int j = 0; j < 32; j += 8) {
        int k = k0 + ty + j, n = n0 + tx;
        tile[ty + j][tx] = (k < K && n < N) ? w[(size_t)k * N + n] : 0.f;
    }
    __syncthreads();
#pragma unroll
    for (int j = 0; j < 32; j += 8) {
        int n = n0 + ty + j, k = k0 + tx;
        if (n < N && k < K) {
            float v = tile[tx][ty + j];
            __half h = __float2half(v);
            Wh[(size_t)n * K + k] = h;
            if (Wl) Wl[(size_t)n * K + k] = __float2half(v - __half2float(h));
        }
    }
}

__global__ void k_bias_cat(const float* __restrict__ b1, const float* __restrict__ b2) {
    int i = threadIdx.x;
    if (i < 144) g_bom[i] = b1[i];
    else if (i < 216) g_bom[i] = b2[i - 144];
}

__global__ void k_dw(const float* __restrict__ dww, const float* __restrict__ dwb,
                     const float* __restrict__ lng, const float* __restrict__ lnb)
{
    int pix = blockIdx.x;
    int c   = threadIdx.x;
    int n = pix >> 12, h = (pix >> 6) & 63, w = pix & 63;
    float acc = dwb[c];
#pragma unroll
    for (int kh = 0; kh < 3; kh++) {
        int y = h + kh - 1;
        if ((unsigned)y >= 64u) continue;
#pragma unroll
        for (int kw = 0; kw < 3; kw++) {
            int x = w + kw - 1;
            if ((unsigned)x >= 64u) continue;
            acc += g_xs[((size_t)((n * 64 + y) * 64 + x)) * 256 + c] *
                   dww[(kh * 3 + kw) * 256 + c];
        }
    }
    __shared__ float sh[32];
    float s = acc, ss = acc * acc;
    block_reduce2(s, ss, sh);
    float mean = s * (1.f / 256.f);
    float var  = ss * (1.f / 256.f) - mean * mean;
    float rstd = rsqrtf(var + 1e-5f);
    float v = (acc - mean) * rstd * lng[c] + lnb[c];
    v = 0.5f * v * (1.f + erff(v * 0.70710678118654752440f));
    __half hh, ll; hsplit(v, hh, ll);
    g_th[(size_t)pix * 256 + c] = hh;
    g_tl[(size_t)pix * 256 + c] = ll;
}

__global__ void k_sample()
{
    int pix  = blockIdx.x;
    int g    = threadIdx.x >> 5;
    int lane = threadIdx.x & 31;
    int n = pix >> 12, h = (pix >> 6) & 63, w = pix & 63;

    const float* ml = g_om + (size_t)pix * 216 + 144 + g * 9;
    float e[9], mx = -1e30f, s = 0.f;
#pragma unroll
    for (int p = 0; p < 9; p++) mx = fmaxf(mx, ml[p]);
#pragma unroll
    for (int p = 0; p < 9; p++) { e[p] = expf(ml[p] - mx); s += e[p]; }
    float inv = 1.f / s;

    const float* off = g_om + (size_t)pix * 216 + g * 18;
    const float* img = g_xp + (size_t)n * HP * HP * CC + g * 32 + lane;
    float acc = 0.f;
#pragma unroll
    for (int p = 0; p < 9; p++) {
        float px = (float)(w + p / 3) + off[2 * p];
        float py = (float)(h + p % 3) + off[2 * p + 1];
        float wgt = e[p] * inv;
        float x0f = floorf(px), y0f = floorf(py);
        int x0 = (int)x0f, y0 = (int)y0f;
        float fx = px - x0f, fy = py - y0f;
#pragma unroll
        for (int dy = 0; dy < 2; dy++) {
            int yy = y0 + dy;
            if ((unsigned)yy >= (unsigned)HP) continue;
            float wy = dy ? fy : 1.f - fy;
#pragma unroll
            for (int dx = 0; dx < 2; dx++) {
                int xx = x0 + dx;
                if ((unsigned)xx >= (unsigned)HP) continue;
                float wx = dx ? fx : 1.f - fx;
                acc += img[((size_t)yy * HP + xx) * CC] * (wx * wy * wgt);
            }
        }
    }
    __half hh, ll; hsplit(acc, hh, ll);
    g_yh[(size_t)pix * 256 + g * 32 + lane] = hh;
    g_yl[(size_t)pix * 256 + g * 32 + lane] = ll;
}

// GroupNorm(32) [+SiLU]; optional second input summed in; fp32/NCHW and/or fp16 out
__global__ void k_gn(const float* __restrict__ in, const float* __restrict__ in2,
                     float* __restrict__ outf,
                     __half* __restrict__ oh,
                     const float* __restrict__ gamma, const float* __restrict__ beta,
                     int HWn, int do_silu, int out_nchw, int Wd)
{
    int n = blockIdx.x >> 5;
    int g = blockIdx.x & 31;
    int cnt = HWn * 8;
    const float* base  = in  + (size_t)n * HWn * 256 + g * 8;
    const float* base2 = in2 ? in2 + (size_t)n * HWn * 256 + g * 8 : nullptr;
    float s = 0.f, ss = 0.f;
    for (int i = threadIdx.x; i < cnt; i += 256) {
        size_t o = (size_t)(i >> 3) * 256 + (i & 7);
        float v = base[o];
        if (base2) v += base2[o];
        s += v; ss += v * v;
    }
    __shared__ float sh[32];
    block_reduce2(s, ss, sh);
    float mean = s / (float)cnt;
    float rstd = rsqrtf(ss / (float)cnt - mean * mean + 1e-5f);
    for (int i = threadIdx.x; i < cnt; i += 256) {
        int l = i >> 3, c = i & 7;
        size_t o = (size_t)l * 256 + c;
        float v = base[o];
        if (base2) v += base2[o];
        v = (v - mean) * rstd * gamma[g * 8 + c] + beta[g * 8 + c];
        if (do_silu) v = v * (1.f / (1.f + expf(-v)));
        if (outf) {
            if (out_nchw)
                outf[(((size_t)n * 256 + g * 8 + c) * Wd + (l / Wd)) * Wd + (l % Wd)] = v;
            else
                outf[((size_t)n * HWn + l) * 256 + g * 8 + c] = v;
        }
        if (oh)
            oh[((size_t)n * HWn + l) * 256 + g * 8 + c] = __float2half(v);
    }
}

// ======================= mma.sync split-fp16 GEMM ============================
// 512 threads, 16 warps (4M x 4N), warp tile 32x32, CTA tile 128x128, BK=64.
// 3-term (Al&&Bl): Ah*Bh + Al*Bh + Ah*Bl, 3 stages (64KB ea), wait(1)
// 2-term (Al only): Ah*Bh + Al*Bh,        4 stages (48KB ea), wait(2)
// 1-term (neither): Ah*Bh,                6 stages (32KB ea), wait(4)
// smem mat order: 0=Ah, 1=Bh, 2=Al|Bl, 3=Bl
#define MATB   16384
#define SM_TOT 196608

__global__ void __launch_bounds__(512, 1)
k_mma(const __half* __restrict__ Ah, const __half* __restrict__ Al,
      const __half* __restrict__ Bh, const __half* __restrict__ Bl,
      const float* __restrict__ bias, float* __restrict__ Cout, float* __restrict__ Cout2,
      int N, int Kloc, int Kfull, int mode, int owbits, int stride, int padout)
{
    extern __shared__ __align__(128) char smem[];
    const uint32_t sb = smem_u32(smem);
    const int tid = threadIdx.x;
    const int wid = tid >> 5, lane = tid & 31;
    const int g = lane >> 2, tg = lane & 3;
    const int warpM = wid & 3, warpN = wid >> 2;
    const int m0 = blockIdx.x * 128;
    const int n0 = blockIdx.y * 128;
    const int kb = blockIdx.z * Kloc;
    float* Cbase = (blockIdx.z == 0) ? Cout : Cout2;
    const float* bias_eff = (blockIdx.z == 0) ? bias : nullptr;
    const bool twoA  = (Al != nullptr);
    const bool three = (Bl != nullptr);
    const int nmats  = 2 + (twoA ? 1 : 0) + (three ? 1 : 0);
    const int depth  = (nmats == 4) ? 3 : (nmats == 3) ? 4 : 6;
    const uint32_t stagesz = (uint32_t)nmats * MATB;
    const int S = Kloc >> 6;

    float acc[2][4][4];
#pragma unroll
    for (int i = 0; i < 2; i++)
#pragma unroll
        for (int j = 0; j < 4; j++)
#pragma unroll
            for (int r = 0; r < 4; r++) acc[i][j][r] = 0.f;

    auto fill = [&](int s, int st) {
        int gk = kb + (s << 6);
        int tap = gk >> 8, ci0 = gk & 255;
        int kh = tap / 3, kw = tap - 3 * kh;
        uint32_t stbase = sb + st * stagesz;
#pragma unroll 4
        for (int q = 0; q < 8; q++) {
            int cid = q * 512 + tid;           // 0..4095
            int mat = cid >> 10;
            if (mat >= nmats) break;
            int idx = cid & 1023;
            int r = idx >> 3, c = idx & 7;
            uint32_t dst = stbase + mat * MATB + r * 128 + ((c ^ (r & 7)) << 4);
            const __half* src;
            int sz = 16;
            bool isA = (mat == 0) || (mat == 2 && twoA);
            if (isA) {
                const __half* Ag = (mat == 0) ? Ah : Al;
                int m = m0 + r;
                if (mode == 0) {
                    src = Ag + (size_t)m * Kfull + gk + c * 8;
                } else {
                    int nn = m >> (2 * owbits);
                    int hw = m & ((1 << (2 * owbits)) - 1);
                    int ohh = hw >> owbits, oww = hw & ((1 << owbits) - 1);
                    int iy = ohh * stride + kh - 1, ix = oww * stride + kw - 1;
                    if ((unsigned)iy < 64u && (unsigned)ix < 64u)
                        src = Ag + ((size_t)((nn * 64 + iy) * 64 + ix)) * 256 + ci0 + c * 8;
                    else { src = Ag; sz = 0; }
                }
            } else {
                const __half* Bg = (mat == 1) ? Bh : Bl;
                int n = n0 + r;
                if (n < N) src = Bg + (size_t)n * Kfull + gk + c * 8;
                else { src = Bg; sz = 0; }
            }
            CP_ASYNC16(dst, src, sz);
        }
    };

    const int lx = lane & 7;
    const uint32_t laneA_row = (uint32_t)(warpM * 32 + lx + ((lane >> 3) & 1) * 8) * 128;
    const uint32_t laneB_row = (uint32_t)(warpN * 32 + lx + ((lane >> 4) & 1) * 8) * 128;
    const int cselA = (lane >> 4) & 1;
    const int cselB = (lane >> 3) & 1;

    auto compute = [&](int st) {
        uint32_t bAh = sb + st * stagesz;
        uint32_t bBh = bAh + MATB;
        uint32_t bAl = bAh + 2 * MATB;
        uint32_t bBl = bAh + (three ? 3 : 2) * MATB;   // 1-term: unused
#pragma unroll
        for (int kk = 0; kk < 4; kk++) {
            uint32_t swzA = (uint32_t)(((kk * 2 + cselA) ^ lx) << 4);
            uint32_t swzB = (uint32_t)(((kk * 2 + cselB) ^ lx) << 4);
            uint32_t ah[2][4], al_[2][4], bh[4][2], bl_[4][2];
#pragma unroll
            for (int mi = 0; mi < 2; mi++) {
                LDSM4(ah[mi][0], ah[mi][1], ah[mi][2], ah[mi][3],
                      bAh + laneA_row + mi * 2048 + swzA);
                if (twoA)
                    LDSM4(al_[mi][0], al_[mi][1], al_[mi][2], al_[mi][3],
                          bAl + laneA_row + mi * 2048 + swzA);
            }
#pragma unroll
            for (int np = 0; np < 2; np++) {
                LDSM4(bh[np*2][0], bh[np*2][1], bh[np*2+1][0], bh[np*2+1][1],
                      bBh + laneB_row + np * 2048 + swzB);
                if (three)
                    LDSM4(bl_[np*2][0], bl_[np*2][1], bl_[np*2+1][0], bl_[np*2+1][1],
                          bBl + laneB_row + np * 2048 + swzB);
            }
#pragma unroll
            for (int mi = 0; mi < 2; mi++)
#pragma unroll
                for (int ni = 0; ni < 4; ni++)
                    MMA_F16(acc[mi][ni], ah[mi], bh[ni]);
            if (twoA) {
#pragma unroll
                for (int mi = 0; mi < 2; mi++)
#pragma unroll
                    for (int ni = 0; ni < 4; ni++)
                        MMA_F16(acc[mi][ni], al_[mi], bh[ni]);
            }
            if (three) {
#pragma unroll
                for (int mi = 0; mi < 2; mi++)
#pragma unroll
                    for (int ni = 0; ni < 4; ni++)
                        MMA_F16(acc[mi][ni], ah[mi], bl_[ni]);
            }
        }
    };

    // multistage pipeline, one barrier per stage
    for (int s = 0; s < depth - 1; s++) { if (s < S) fill(s, s); CP_COMMIT(); }
    int st = 0;
    for (int s = 0; s < S; s++) {
        if (nmats == 4) CP_WAIT(1);
        else if (nmats == 3) CP_WAIT(2);
        else CP_WAIT(4);
        __syncthreads();
        int stf = st + depth - 1; if (stf >= depth) stf -= depth;
        if (s + depth - 1 < S) fill(s + depth - 1, stf);
        CP_COMMIT();
        compute(st);
        if (++st == depth) st = 0;
    }

    // ---- epilogue ----
#pragma unroll
    for (int mi = 0; mi < 2; mi++) {
        int mA = m0 + warpM * 32 + mi * 16 + g;
#pragma unroll
        for (int half = 0; half < 2; half++) {
            int m = mA + half * 8;
            float* orow;
            if (padout) {
                int n = m >> 12, h = (m >> 6) & 63, w = m & 63;
                orow = Cbase + ((size_t)(n * HP + h + 1) * HP + (w + 1)) * 256;
            } else {
                orow = Cbase + (size_t)m * N;
            }
#pragma unroll
            for (int ni = 0; ni < 4; ni++) {
                int nc = n0 + warpN * 32 + ni * 8 + tg * 2;
                float b0 = bias_eff ? bias_eff[nc < N ? nc : 0] : 0.f;
                float b1 = bias_eff ? bias_eff[nc + 1 < N ? nc + 1 : 0] : 0.f;
                if (nc < N)     orow[nc]     = acc[mi][ni][half * 2]     + b0;
                if (nc + 1 < N) orow[nc + 1] = acc[mi][ni][half * 2 + 1] + b1;
            }
        }
    }
}

// ======================= launch =============================================
extern "C" void kernel_launch(void* const* d_in, const int* in_sizes, int n_in,
                              void* d_out, int out_size)
{
    const float* x      = (const float*)d_in[0];
    const float* w_in   = (const float*)d_in[1];
    const float* b_in   = (const float*)d_in[2];
    const float* dw_w   = (const float*)d_in[3];
    const float* dw_b   = (const float*)d_in[4];
    const float* ln_g   = (const float*)d_in[5];
    const float* ln_b   = (const float*)d_in[6];
    const float* w_off  = (const float*)d_in[7];
    const float* b_off  = (const float*)d_in[8];
    const float* w_mask = (const float*)d_in[9];
    const float* b_mask = (const float*)d_in[10];
    const float* w_out  = (const float*)d_in[11];
    const float* b_out  = (const float*)d_in[12];
    const float* gn1_g  = (const float*)d_in[13];
    const float* gn1_b  = (const float*)d_in[14];
    const float* c1_w   = (const float*)d_in[15];
    const float* c1_b   = (const float*)d_in[16];
    const float* gn2_g  = (const float*)d_in[17];
    const float* gn2_b  = (const float*)d_in[18];
    const float* dn_w   = (const float*)d_in[19];
    const float* dn_b   = (const float*)d_in[20];
    const float* gn3_g  = (const float*)d_in[21];
    const float* gn3_b  = (const float*)d_in[22];

    cudaFuncSetAttribute(k_mma, cudaFuncAttributeMaxDynamicSharedMemorySize, SM_TOT);

    float *xp, *om, *bom, *y2, *dn;
    __half *xsh, *xsl, *th, *tl, *yh, *yl, *gh;
    __half *winh, *winl, *omh, *oml, *wouh, *woul, *c1h, *dnh;
    cudaGetSymbolAddress((void**)&xp,  g_xp);
    cudaGetSymbolAddress((void**)&om,  g_om);
    cudaGetSymbolAddress((void**)&bom, g_bom);
    cudaGetSymbolAddress((void**)&y2,  g_y2);
    cudaGetSymbolAddress((void**)&dn,  g_dn);
    cudaGetSymbolAddress((void**)&xsh, g_xsh); cudaGetSymbolAddress((void**)&xsl, g_xsl);
    cudaGetSymbolAddress((void**)&th,  g_th);  cudaGetSymbolAddress((void**)&tl,  g_tl);
    cudaGetSymbolAddress((void**)&yh,  g_yh);  cudaGetSymbolAddress((void**)&yl,  g_yl);
    cudaGetSymbolAddress((void**)&gh,  g_gh);
    cudaGetSymbolAddress((void**)&winh, g_winh); cudaGetSymbolAddress((void**)&winl, g_winl);
    cudaGetSymbolAddress((void**)&omh,  g_omh);  cudaGetSymbolAddress((void**)&oml,  g_oml);
    cudaGetSymbolAddress((void**)&wouh, g_wouh); cudaGetSymbolAddress((void**)&woul, g_woul);
    cudaGetSymbolAddress((void**)&c1h,  g_c1h);  cudaGetSymbolAddress((void**)&dnh,  g_dnh);

    dim3 wblk(32, 8);
    k_transpose<<<dim3(8, 128, 4), wblk>>>(x);                                   // 0
    k_zero_xp<<<(NB * HP * HP * CC / 4 + 255) / 256, 256>>>();                   // 1
    k_wprep<<<dim3(8, 8), wblk>>>(w_in, winh, winl, 256, 256);                   // 2
    // 3: input projection -> padded xp (3-term)   [PROFILED LAUNCH]
    k_mma<<<dim3(128, 2, 1), 512, SM_TOT>>>(xsh, xsl, winh, winl, b_in, xp, nullptr,
                                            256, 256, 256, 0, 0, 0, 1);
    // remaining weight preps
    k_wprep<<<dim3(8, 5), wblk>>>(w_off,  omh,             oml,             256, 144);
    k_wprep<<<dim3(8, 3), wblk>>>(w_mask, omh + 144 * 256, oml + 144 * 256, 256, 72);
    k_bias_cat<<<1, 256>>>(b_off, b_mask);
    k_wprep<<<dim3(8, 8),  wblk>>>(w_out, wouh, woul, 256, 256);
    k_wprep<<<dim3(72, 8), wblk>>>(c1_w, c1h, (__half*)nullptr, 2304, 256);
    k_wprep<<<dim3(72, 8), wblk>>>(dn_w, dnh, (__half*)nullptr, 2304, 256);
    // depthwise + LN + GELU -> t (fp16 split)
    k_dw<<<NPIX, 256>>>(dw_w, dw_b, ln_g, ln_b);
    // fused offset+mask projection (N=216, 3-term)
    k_mma<<<dim3(128, 2, 1), 512, SM_TOT>>>(th, tl, omh, oml, bom, om, nullptr,
                                            216, 256, 256, 0, 0, 0, 0);
    // deformable sampling -> y (fp16 split)
    k_sample<<<NPIX, 256>>>();
    // output projection -> y2 (3-term)
    k_mma<<<dim3(128, 2, 1), 512, SM_TOT>>>(yh, yl, wouh, woul, b_out, y2, nullptr,
                                            256, 256, 256, 0, 0, 0, 0);
    // GN1 + SiLU -> fp16 (hi only)
    k_gn<<<128, 256>>>(y2, nullptr, (float*)nullptr, gh, gn1_g, gn1_b, 4096, 1, 0, 64);
    // conv1 3x3 implicit im2col (K=2304, 1-term fp16, 6-stage) -> y2
    k_mma<<<dim3(128, 2, 1), 512, SM_TOT>>>(gh, nullptr, c1h, nullptr, c1_b, y2, nullptr,
                                            256, 2304, 2304, 1, 6, 1, 0);
    // GN2 + SiLU -> fp16 (hi only)
    k_gn<<<128, 256>>>(y2, nullptr, (float*)nullptr, gh, gn2_g, gn2_b, 4096, 1, 0, 64);
    // down conv 3x3 stride2 (1-term, K-split z=2: dn + partial in y2)
    k_mma<<<dim3(32, 2, 2), 512, SM_TOT>>>(gh, nullptr, dnh, nullptr, dn_b, dn, y2,
                                           256, 1152, 2304, 1, 5, 2, 0);
    // GN3 (sums dn + y2 partial) -> NCHW output
    k_gn<<<128, 256>>>(dn, y2, (float*)d_out, (__half*)nullptr,
                       gn3_g, gn3_b, 1024, 0, 1, 32);
}